// round 3
// baseline (speedup 1.0000x reference)
#include <cuda_runtime.h>
#include <math.h>

#define N_NODE 80000
#define N_NET  20000
#define NEDGE  150000
#define HD     32      // node/net hidden + out dims
#define HE     16      // pin/edge feature dims
#define WROWS  (HD*HD) // 1024 rows of the edge-MLP weight
#define WSZ    (WROWS*HE)

typedef unsigned long long u64;

// ---- packed f32x2 helpers (FFMA2: sm_103a, PTX-only) ----
__device__ __forceinline__ u64 pack2(float lo, float hi) {
    u64 r; asm("mov.b64 %0, {%1, %2};" : "=l"(r) : "f"(lo), "f"(hi)); return r;
}
__device__ __forceinline__ u64 fma2(u64 a, u64 b, u64 c) {
    u64 d; asm("fma.rn.f32x2 %0, %1, %2, %3;" : "=l"(d) : "l"(a), "l"(b), "l"(c)); return d;
}
__device__ __forceinline__ u64 mul2(u64 a, u64 b) {
    u64 d; asm("mul.rn.f32x2 %0, %1, %2;" : "=l"(d) : "l"(a), "l"(b)); return d;
}
__device__ __forceinline__ void unpack2(u64 v, float& lo, float& hi) {
    asm("mov.b64 {%0, %1}, %2;" : "=f"(lo), "=f"(hi) : "l"(v));
}

// ---- scratch (device globals; no allocation allowed) ----
__device__ float g_deg_out[N_NODE];
__device__ float g_deg_in [N_NET];
__device__ float g_deg_p  [N_NODE];
__device__ float g_deg_n  [N_NODE];
__device__ float g_agg    [N_NET * HD];
__device__ float g_accp   [N_NODE * HD];
__device__ float g_accn   [N_NODE * HD];

// ---------------------------------------------------------------------------
__global__ void k_zero() {
    int stride = gridDim.x * blockDim.x;
    int i0 = blockIdx.x * blockDim.x + threadIdx.x;
    for (int j = i0; j < N_NODE; j += stride) {
        g_deg_out[j] = 0.f; g_deg_p[j] = 0.f; g_deg_n[j] = 0.f;
    }
    for (int j = i0; j < N_NET; j += stride) g_deg_in[j] = 0.f;
    for (int j = i0; j < N_NET * HD; j += stride) g_agg[j] = 0.f;
    for (int j = i0; j < N_NODE * HD; j += stride) {
        g_accp[j] = 0.f; g_accn[j] = 0.f;
    }
}

// ---------------------------------------------------------------------------
__global__ void k_deg(const int* __restrict__ ps, const int* __restrict__ pd,
                      const int* __restrict__ pnd, const int* __restrict__ nrd) {
    int e = blockIdx.x * blockDim.x + threadIdx.x;
    if (e >= NEDGE) return;
    atomicAdd(&g_deg_out[ps[e]],  1.f);
    atomicAdd(&g_deg_in [pd[e]],  1.f);
    atomicAdd(&g_deg_p  [pnd[e]], 1.f);
    atomicAdd(&g_deg_n  [nrd[e]], 1.f);
}

// ---------------------------------------------------------------------------
__global__ void k_pins(const float* __restrict__ nodef,
                       const int* __restrict__ src, const int* __restrict__ dst) {
    int t = blockIdx.x * blockDim.x + threadIdx.x;
    if (t >= NEDGE * HD) return;
    int e = t >> 5, c = t & 31;
    int s = src[e];
    float nrm = rsqrtf(fmaxf(g_deg_out[s], 1.f));
    atomicAdd(&g_agg[(size_t)dst[e] * HD + c], nodef[(size_t)s * HD + c] * nrm);
}

// ---------------------------------------------------------------------------
__global__ void k_netout(const float* __restrict__ gcw, const float* __restrict__ gcb,
                         float* __restrict__ out) {
    int t = blockIdx.x * blockDim.x + threadIdx.x;
    if (t >= N_NET * HD) return;
    int n = t >> 5, o = t & 31;
    float nrm = rsqrtf(fmaxf(g_deg_in[n], 1.f));
    float a = 0.f;
    #pragma unroll
    for (int d = 0; d < HD; d++)
        a = fmaf(g_agg[n * HD + d], gcw[d * HD + o], a);
    out[(size_t)N_NODE * HD + t] = a * nrm + gcb[o];
}

// ---------------------------------------------------------------------------
// NNConv edge kernel, packed-f32x2 Z-formulation, LDS.128 weight loads.
//   msg[o] = sum_{i,k} (nf[i]*pf[k]) * W[(i,o),k]  +  sum_i nf[i]*b[i,o]
// 16 f32x2 accumulators (pairs o,o+1). Weights in transposed smem
// wsT[(i*16+k)*32 + o]; each ulonglong2 LDS.128 (lane-uniform -> broadcast)
// yields two f32x2 operands. Z scalar nf[i]*pf[k] duplicated via mul2.
__global__ void __launch_bounds__(128)
k_nnconv(const float* __restrict__ srcfeat,
         const float* __restrict__ efeat,
         const float* __restrict__ w, const float* __restrict__ b,
         const int* __restrict__ src, const int* __restrict__ dst,
         float* __restrict__ acc) {
    extern __shared__ float sm[];
    float* wsT = sm;          // 16384 floats: [i*16+k][o]
    float* bsS = sm + WSZ;    // 1024 floats:  [i][o]
    for (int idx = threadIdx.x; idx < WSZ; idx += blockDim.x) {
        int r = idx >> 4, k = idx & 15;    // source row-major: row r = i*32+o
        int i = r >> 5, o = r & 31;
        wsT[((i << 4) + k) * HD + o] = w[idx];
    }
    for (int idx = threadIdx.x; idx < WROWS; idx += blockDim.x) bsS[idx] = b[idx];
    __syncthreads();

    int e = blockIdx.x * blockDim.x + threadIdx.x;
    if (e >= NEDGE) return;
    int s = src[e];
    int d = dst[e];

    float nf[HD];
    {
        const float4* r = reinterpret_cast<const float4*>(srcfeat + (size_t)s * HD);
        #pragma unroll
        for (int i = 0; i < HD / 4; i++) {
            float4 v = r[i];
            nf[4*i] = v.x; nf[4*i+1] = v.y; nf[4*i+2] = v.z; nf[4*i+3] = v.w;
        }
    }
    u64 pfd[HE];   // {pf[k], pf[k]}
    {
        const float4* r = reinterpret_cast<const float4*>(efeat + (size_t)e * HE);
        #pragma unroll
        for (int k = 0; k < HE / 4; k++) {
            float4 v = r[k];
            pfd[4*k+0] = pack2(v.x, v.x);
            pfd[4*k+1] = pack2(v.y, v.y);
            pfd[4*k+2] = pack2(v.z, v.z);
            pfd[4*k+3] = pack2(v.w, v.w);
        }
    }

    u64 msg2[HD / 2];
    #pragma unroll
    for (int op = 0; op < HD / 2; op++) msg2[op] = 0ull;   // packed {0,0}

    #pragma unroll 1
    for (int i = 0; i < HD; i++) {
        u64 nfi = pack2(nf[i], nf[i]);

        // bias: msg2 += nf[i] * {b[i,2op], b[i,2op+1]}  (8x LDS.128)
        const ulonglong2* b4 = reinterpret_cast<const ulonglong2*>(bsS + i * HD);
        #pragma unroll
        for (int q = 0; q < HD / 4; q++) {
            ulonglong2 bb = b4[q];
            msg2[2*q+0] = fma2(nfi, bb.x, msg2[2*q+0]);
            msg2[2*q+1] = fma2(nfi, bb.y, msg2[2*q+1]);
        }

        // Z row: z[k] = {nf[i]*pf[k]} duplicated
        u64 z[HE];
        #pragma unroll
        for (int k = 0; k < HE; k++) z[k] = mul2(nfi, pfd[k]);

        const ulonglong2* w4 =
            reinterpret_cast<const ulonglong2*>(wsT + i * (HE * HD));
        #pragma unroll
        for (int k = 0; k < HE; k++) {
            #pragma unroll
            for (int q = 0; q < HD / 4; q++) {      // 8 LDS.128 per k
                ulonglong2 ww = w4[k * (HD / 4) + q];
                msg2[2*q+0] = fma2(z[k], ww.x, msg2[2*q+0]);
                msg2[2*q+1] = fma2(z[k], ww.y, msg2[2*q+1]);
            }
        }
    }

    float* ap = acc + (size_t)d * HD;
    #pragma unroll
    for (int op = 0; op < HD / 2; op++) {
        float lo, hi; unpack2(msg2[op], lo, hi);
        atomicAdd(ap + 2*op + 0, lo);
        atomicAdd(ap + 2*op + 1, hi);
    }
}

// ---------------------------------------------------------------------------
__global__ void k_final(const float* __restrict__ pb, const float* __restrict__ nb,
                        float* __restrict__ out) {
    int t = blockIdx.x * blockDim.x + threadIdx.x;
    if (t >= N_NODE * HD) return;
    int n = t >> 5, o = t & 31;
    float p = g_accp[t] / fmaxf(g_deg_p[n], 1.f) + pb[o];
    float q = g_accn[t] / fmaxf(g_deg_n[n], 1.f) + nb[o];
    out[t] = fmaxf(p, q);
}

// ---------------------------------------------------------------------------
extern "C" void kernel_launch(void* const* d_in, const int* in_sizes, int n_in,
                              void* d_out, int out_size) {
    const float* node_feat = (const float*)d_in[0];
    const float* net_feat  = (const float*)d_in[1];
    const float* pin_feat  = (const float*)d_in[2];
    const float* edge_feat = (const float*)d_in[3];
    const float* topo_w    = (const float*)d_in[4];
    const float* topo_b    = (const float*)d_in[5];
    const float* geom_w    = (const float*)d_in[6];
    const float* geom_b    = (const float*)d_in[7];
    const float* gc_w      = (const float*)d_in[8];
    const float* gc_b      = (const float*)d_in[9];
    const float* pinned_b  = (const float*)d_in[10];
    const float* near_b    = (const float*)d_in[11];
    const int* pins_src    = (const int*)d_in[12];
    const int* pins_dst    = (const int*)d_in[13];
    const int* pinned_src  = (const int*)d_in[14];
    const int* pinned_dst  = (const int*)d_in[15];
    const int* near_src    = (const int*)d_in[16];
    const int* near_dst    = (const int*)d_in[17];
    float* out = (float*)d_out;

    const int smem = (WSZ + WROWS) * (int)sizeof(float);   // 69632 B
    cudaFuncSetAttribute(k_nnconv, cudaFuncAttributeMaxDynamicSharedMemorySize, smem);

    float *accp_ptr = nullptr, *accn_ptr = nullptr;
    cudaGetSymbolAddress((void**)&accp_ptr, g_accp);
    cudaGetSymbolAddress((void**)&accn_ptr, g_accn);

    k_zero<<<512, 256>>>();
    k_deg<<<(NEDGE + 255) / 256, 256>>>(pins_src, pins_dst, pinned_dst, near_dst);
    k_pins<<<(NEDGE * HD + 255) / 256, 256>>>(node_feat, pins_src, pins_dst);
    k_netout<<<(N_NET * HD + 255) / 256, 256>>>(gc_w, gc_b, out);

    int nb = (NEDGE + 127) / 128;
    k_nnconv<<<nb, 128, smem>>>(net_feat,  pin_feat,  topo_w, topo_b,
                                pinned_src, pinned_dst, accp_ptr);
    k_nnconv<<<nb, 128, smem>>>(node_feat, edge_feat, geom_w, geom_b,
                                near_src,  near_dst,  accn_ptr);

    k_final<<<(N_NODE * HD + 255) / 256, 256>>>(pinned_b, near_b, out);
}

// round 4
// speedup vs baseline: 1.2578x; 1.2578x over previous
#include <cuda_runtime.h>
#include <math.h>

#define N_NODE 80000
#define N_NET  20000
#define NEDGE  150000
#define HD     32      // node/net hidden + out dims
#define HE     16      // pin/edge feature dims
#define WROWS  (HD*HD) // 1024 rows of the edge-MLP weight
#define WSZ    (WROWS*HE)

typedef unsigned long long u64;

// ---- packed f32x2 helpers (FFMA2: sm_103a, PTX-only) ----
__device__ __forceinline__ u64 pack2(float lo, float hi) {
    u64 r; asm("mov.b64 %0, {%1, %2};" : "=l"(r) : "f"(lo), "f"(hi)); return r;
}
__device__ __forceinline__ u64 fma2(u64 a, u64 b, u64 c) {
    u64 d; asm("fma.rn.f32x2 %0, %1, %2, %3;" : "=l"(d) : "l"(a), "l"(b), "l"(c)); return d;
}
__device__ __forceinline__ u64 mul2(u64 a, u64 b) {
    u64 d; asm("mul.rn.f32x2 %0, %1, %2;" : "=l"(d) : "l"(a), "l"(b)); return d;
}
__device__ __forceinline__ void unpack2(u64 v, float& lo, float& hi) {
    asm("mov.b64 {%0, %1}, %2;" : "=f"(lo), "=f"(hi) : "l"(v));
}

// ---- scratch (device globals; no allocation allowed) ----
__device__ float g_deg_out[N_NODE];
__device__ float g_deg_in [N_NET];
__device__ float g_deg_p  [N_NODE];
__device__ float g_deg_n  [N_NODE];
__device__ float g_agg    [N_NET * HD];
__device__ float g_accp   [N_NODE * HD];
__device__ float g_accn   [N_NODE * HD];

// ---------------------------------------------------------------------------
__global__ void k_zero() {
    int stride = gridDim.x * blockDim.x;
    int i0 = blockIdx.x * blockDim.x + threadIdx.x;
    for (int j = i0; j < N_NODE; j += stride) {
        g_deg_out[j] = 0.f; g_deg_p[j] = 0.f; g_deg_n[j] = 0.f;
    }
    for (int j = i0; j < N_NET; j += stride) g_deg_in[j] = 0.f;
    for (int j = i0; j < N_NET * HD; j += stride) g_agg[j] = 0.f;
    for (int j = i0; j < N_NODE * HD; j += stride) {
        g_accp[j] = 0.f; g_accn[j] = 0.f;
    }
}

// ---------------------------------------------------------------------------
__global__ void k_deg(const int* __restrict__ ps, const int* __restrict__ pd,
                      const int* __restrict__ pnd, const int* __restrict__ nrd) {
    int e = blockIdx.x * blockDim.x + threadIdx.x;
    if (e >= NEDGE) return;
    atomicAdd(&g_deg_out[ps[e]],  1.f);
    atomicAdd(&g_deg_in [pd[e]],  1.f);
    atomicAdd(&g_deg_p  [pnd[e]], 1.f);
    atomicAdd(&g_deg_n  [nrd[e]], 1.f);
}

// ---------------------------------------------------------------------------
__global__ void k_pins(const float* __restrict__ nodef,
                       const int* __restrict__ src, const int* __restrict__ dst) {
    int t = blockIdx.x * blockDim.x + threadIdx.x;
    if (t >= NEDGE * HD) return;
    int e = t >> 5, c = t & 31;
    int s = src[e];
    float nrm = rsqrtf(fmaxf(g_deg_out[s], 1.f));
    atomicAdd(&g_agg[(size_t)dst[e] * HD + c], nodef[(size_t)s * HD + c] * nrm);
}

// ---------------------------------------------------------------------------
__global__ void k_netout(const float* __restrict__ gcw, const float* __restrict__ gcb,
                         float* __restrict__ out) {
    int t = blockIdx.x * blockDim.x + threadIdx.x;
    if (t >= N_NET * HD) return;
    int n = t >> 5, o = t & 31;
    float nrm = rsqrtf(fmaxf(g_deg_in[n], 1.f));
    float a = 0.f;
    #pragma unroll
    for (int d = 0; d < HD; d++)
        a = fmaf(g_agg[n * HD + d], gcw[d * HD + o], a);
    out[(size_t)N_NODE * HD + t] = a * nrm + gcb[o];
}

// ---------------------------------------------------------------------------
// NNConv edge kernel, packed-f32x2 Z-formulation, LDS.128 weight loads,
// register-lean (no z[] array, no duplicated nf array), 256 thr / 2 CTAs per SM.
//   msg[o] = sum_{i,k} (nf[i]*pf[k]) * W[(i,o),k]  +  sum_i nf[i]*b[i,o]
__global__ void __launch_bounds__(256, 2)
k_nnconv(const float* __restrict__ srcfeat,
         const float* __restrict__ efeat,
         const float* __restrict__ w, const float* __restrict__ b,
         const int* __restrict__ src, const int* __restrict__ dst,
         float* __restrict__ acc) {
    extern __shared__ float sm[];
    float* wsT = sm;          // 16384 floats: [i*16+k][o]
    float* bsS = sm + WSZ;    // 1024 floats:  [i][o]
    for (int idx = threadIdx.x; idx < WSZ; idx += blockDim.x) {
        int r = idx >> 4, k = idx & 15;    // source row-major: row r = i*32+o
        int i = r >> 5, o = r & 31;
        wsT[((i << 4) + k) * HD + o] = w[idx];
    }
    for (int idx = threadIdx.x; idx < WROWS; idx += blockDim.x) bsS[idx] = b[idx];
    __syncthreads();

    int e = blockIdx.x * blockDim.x + threadIdx.x;
    if (e >= NEDGE) return;
    int s = src[e];
    int d = dst[e];

    float nf[HD];
    {
        const float4* r = reinterpret_cast<const float4*>(srcfeat + (size_t)s * HD);
        #pragma unroll
        for (int i = 0; i < HD / 4; i++) {
            float4 v = r[i];
            nf[4*i] = v.x; nf[4*i+1] = v.y; nf[4*i+2] = v.z; nf[4*i+3] = v.w;
        }
    }
    u64 pfd[HE];   // {pf[k], pf[k]}
    {
        const float4* r = reinterpret_cast<const float4*>(efeat + (size_t)e * HE);
        #pragma unroll
        for (int k = 0; k < HE / 4; k++) {
            float4 v = r[k];
            pfd[4*k+0] = pack2(v.x, v.x);
            pfd[4*k+1] = pack2(v.y, v.y);
            pfd[4*k+2] = pack2(v.z, v.z);
            pfd[4*k+3] = pack2(v.w, v.w);
        }
    }

    u64 msg2[HD / 2];
    #pragma unroll
    for (int op = 0; op < HD / 2; op++) msg2[op] = 0ull;   // packed {0,0}

    #pragma unroll 1
    for (int i = 0; i < HD; i++) {
        u64 nfi = pack2(nf[i], nf[i]);

        // bias: msg2 += nf[i] * {b[i,2op], b[i,2op+1]}  (8x LDS.128)
        const ulonglong2* b4 = reinterpret_cast<const ulonglong2*>(bsS + i * HD);
        #pragma unroll
        for (int q = 0; q < HD / 4; q++) {
            ulonglong2 bb = b4[q];
            msg2[2*q+0] = fma2(nfi, bb.x, msg2[2*q+0]);
            msg2[2*q+1] = fma2(nfi, bb.y, msg2[2*q+1]);
        }

        const ulonglong2* w4 =
            reinterpret_cast<const ulonglong2*>(wsT + i * (HE * HD));
        #pragma unroll
        for (int k = 0; k < HE; k++) {
            u64 zk = mul2(nfi, pfd[k]);            // {nf[i]*pf[k]} x2, short-lived
            #pragma unroll
            for (int q = 0; q < HD / 4; q++) {     // 8 LDS.128 per k
                ulonglong2 ww = w4[k * (HD / 4) + q];
                msg2[2*q+0] = fma2(zk, ww.x, msg2[2*q+0]);
                msg2[2*q+1] = fma2(zk, ww.y, msg2[2*q+1]);
            }
        }
    }

    float* ap = acc + (size_t)d * HD;
    #pragma unroll
    for (int op = 0; op < HD / 2; op++) {
        float lo, hi; unpack2(msg2[op], lo, hi);
        atomicAdd(ap + 2*op + 0, lo);
        atomicAdd(ap + 2*op + 1, hi);
    }
}

// ---------------------------------------------------------------------------
__global__ void k_final(const float* __restrict__ pb, const float* __restrict__ nb,
                        float* __restrict__ out) {
    int t = blockIdx.x * blockDim.x + threadIdx.x;
    if (t >= N_NODE * HD) return;
    int n = t >> 5, o = t & 31;
    float p = g_accp[t] / fmaxf(g_deg_p[n], 1.f) + pb[o];
    float q = g_accn[t] / fmaxf(g_deg_n[n], 1.f) + nb[o];
    out[t] = fmaxf(p, q);
}

// ---------------------------------------------------------------------------
extern "C" void kernel_launch(void* const* d_in, const int* in_sizes, int n_in,
                              void* d_out, int out_size) {
    const float* node_feat = (const float*)d_in[0];
    const float* net_feat  = (const float*)d_in[1];
    const float* pin_feat  = (const float*)d_in[2];
    const float* edge_feat = (const float*)d_in[3];
    const float* topo_w    = (const float*)d_in[4];
    const float* topo_b    = (const float*)d_in[5];
    const float* geom_w    = (const float*)d_in[6];
    const float* geom_b    = (const float*)d_in[7];
    const float* gc_w      = (const float*)d_in[8];
    const float* gc_b      = (const float*)d_in[9];
    const float* pinned_b  = (const float*)d_in[10];
    const float* near_b    = (const float*)d_in[11];
    const int* pins_src    = (const int*)d_in[12];
    const int* pins_dst    = (const int*)d_in[13];
    const int* pinned_src  = (const int*)d_in[14];
    const int* pinned_dst  = (const int*)d_in[15];
    const int* near_src    = (const int*)d_in[16];
    const int* near_dst    = (const int*)d_in[17];
    float* out = (float*)d_out;

    const int smem = (WSZ + WROWS) * (int)sizeof(float);   // 69632 B
    cudaFuncSetAttribute(k_nnconv, cudaFuncAttributeMaxDynamicSharedMemorySize, smem);

    float *accp_ptr = nullptr, *accn_ptr = nullptr;
    cudaGetSymbolAddress((void**)&accp_ptr, g_accp);
    cudaGetSymbolAddress((void**)&accn_ptr, g_accn);

    k_zero<<<512, 256>>>();
    k_deg<<<(NEDGE + 255) / 256, 256>>>(pins_src, pins_dst, pinned_dst, near_dst);
    k_pins<<<(NEDGE * HD + 255) / 256, 256>>>(node_feat, pins_src, pins_dst);
    k_netout<<<(N_NET * HD + 255) / 256, 256>>>(gc_w, gc_b, out);

    int nb = (NEDGE + 255) / 256;
    k_nnconv<<<nb, 256, smem>>>(net_feat,  pin_feat,  topo_w, topo_b,
                                pinned_src, pinned_dst, accp_ptr);
    k_nnconv<<<nb, 256, smem>>>(node_feat, edge_feat, geom_w, geom_b,
                                near_src,  near_dst,  accn_ptr);

    k_final<<<(N_NODE * HD + 255) / 256, 256>>>(pinned_b, near_b, out);
}

// round 6
// speedup vs baseline: 2.4216x; 1.9252x over previous
#include <cuda_runtime.h>
#include <cuda_bf16.h>
#include <math.h>
#include <stdint.h>

#define N_NODE 80000
#define N_NET  20000
#define NEDGE  150000
#define HD     32
#define HE     16

#define TILE_M 128
#define NTILES ((NEDGE + TILE_M - 1) / TILE_M)   // 1172
#define NFRAG  (HD * 4 * 32)                      // 4096 fragment slots (i, nb, lane)

// smem layout (bytes)
#define NF_STRIDE 33
#define NF_BYTES  (TILE_M * NF_STRIDE * 4)        // 16896 (16-aligned)
#define FH_OFF    NF_BYTES
#define FL_OFF    (NF_BYTES + NFRAG * 8)          // +32768
#define SM_TOT    (NF_BYTES + 2 * NFRAG * 8)      // 82432

typedef unsigned int u32;

// ---------------- helpers ----------------
__device__ __forceinline__ u32 bf16pair(float lo, float hi) {
    u32 r;  // cvt.rn.bf16x2.f32 d, a, b -> d = {hi=a, lo=b}
    asm("cvt.rn.bf16x2.f32 %0, %1, %2;" : "=r"(r) : "f"(hi), "f"(lo));
    return r;
}
__device__ __forceinline__ u32 packlo_resid(u32 h, float z0, float z1) {
    float r0 = z0 - __uint_as_float(h << 16);
    float r1 = z1 - __uint_as_float(h & 0xFFFF0000u);
    return bf16pair(r0, r1);
}
__device__ __forceinline__ void mma_bf16(float* d, u32 a0, u32 a1, u32 a2, u32 a3,
                                         u32 b0, u32 b1) {
    asm volatile(
        "mma.sync.aligned.m16n8k16.row.col.f32.bf16.bf16.f32 "
        "{%0,%1,%2,%3}, {%4,%5,%6,%7}, {%8,%9}, {%0,%1,%2,%3};"
        : "+f"(d[0]), "+f"(d[1]), "+f"(d[2]), "+f"(d[3])
        : "r"(a0), "r"(a1), "r"(a2), "r"(a3), "r"(b0), "r"(b1));
}

// ---- scratch (device globals; no allocation allowed) ----
__device__ float g_deg_out[N_NODE];
__device__ float g_deg_in [N_NET];
__device__ float g_deg_p  [N_NODE];
__device__ float g_deg_n  [N_NODE];
__device__ float g_agg    [N_NET * HD];
__device__ float g_accp   [N_NODE * HD];
__device__ float g_accn   [N_NODE * HD];
__device__ float g_btp    [N_NET  * HD];
__device__ float g_btn    [N_NODE * HD];
__device__ __align__(16) uint2 g_fh_p[NFRAG];
__device__ __align__(16) uint2 g_fl_p[NFRAG];
__device__ __align__(16) uint2 g_fh_n[NFRAG];
__device__ __align__(16) uint2 g_fl_n[NFRAG];

// ---------------------------------------------------------------------------
__global__ void k_zero() {
    int stride = gridDim.x * blockDim.x;
    int i0 = blockIdx.x * blockDim.x + threadIdx.x;
    for (int j = i0; j < N_NODE; j += stride) {
        g_deg_out[j] = 0.f; g_deg_p[j] = 0.f; g_deg_n[j] = 0.f;
    }
    for (int j = i0; j < N_NET; j += stride) g_deg_in[j] = 0.f;
    for (int j = i0; j < N_NET * HD; j += stride) g_agg[j] = 0.f;
    for (int j = i0; j < N_NODE * HD; j += stride) {
        g_accp[j] = 0.f; g_accn[j] = 0.f;
    }
}

// ---------------------------------------------------------------------------
__global__ void k_deg(const int* __restrict__ ps, const int* __restrict__ pd,
                      const int* __restrict__ pnd, const int* __restrict__ nrd) {
    int e = blockIdx.x * blockDim.x + threadIdx.x;
    if (e >= NEDGE) return;
    atomicAdd(&g_deg_out[ps[e]],  1.f);
    atomicAdd(&g_deg_in [pd[e]],  1.f);
    atomicAdd(&g_deg_p  [pnd[e]], 1.f);
    atomicAdd(&g_deg_n  [nrd[e]], 1.f);
}

// ---------------------------------------------------------------------------
__global__ void k_pins(const float* __restrict__ nodef,
                       const int* __restrict__ src, const int* __restrict__ dst) {
    int t = blockIdx.x * blockDim.x + threadIdx.x;
    if (t >= NEDGE * HD) return;
    int e = t >> 5, c = t & 31;
    int s = src[e];
    float nrm = rsqrtf(fmaxf(g_deg_out[s], 1.f));
    atomicAdd(&g_agg[(size_t)dst[e] * HD + c], nodef[(size_t)s * HD + c] * nrm);
}

// ---------------------------------------------------------------------------
__global__ void k_netout(const float* __restrict__ gcw, const float* __restrict__ gcb,
                         float* __restrict__ out) {
    int t = blockIdx.x * blockDim.x + threadIdx.x;
    if (t >= N_NET * HD) return;
    int n = t >> 5, o = t & 31;
    float nrm = rsqrtf(fmaxf(g_deg_in[n], 1.f));
    float a = 0.f;
    #pragma unroll
    for (int d = 0; d < HD; d++)
        a = fmaf(g_agg[n * HD + d], gcw[d * HD + o], a);
    out[(size_t)N_NODE * HD + t] = a * nrm + gcb[o];
}

// ---------------------------------------------------------------------------
// Precompute B fragments (hi/lo bf16 split) in exact m16n8k16 .col layout.
// Fragment slot (i, nb, lane): lane holds B[(k0, o), (k0+1, o)] and k0+8 pair,
// where k0 = (lane%4)*2, o = nb*8 + lane/4, B[k,o] = W[(i*32+o)*16 + k].
__global__ void k_wprep(const float* __restrict__ w,
                        uint2* __restrict__ fh, uint2* __restrict__ fl) {
    int idx = blockIdx.x * blockDim.x + threadIdx.x;
    if (idx >= NFRAG) return;
    int lane = idx & 31, nb = (idx >> 5) & 3, i = idx >> 7;
    int o = nb * 8 + (lane >> 2);
    int k0 = (lane & 3) * 2;
    const float* row = w + ((size_t)i * HD + o) * HE;
    float W00 = row[k0],     W01 = row[k0 + 1];
    float W08 = row[k0 + 8], W09 = row[k0 + 9];
    u32 b0h = bf16pair(W00, W01);
    u32 b1h = bf16pair(W08, W09);
    fh[idx] = make_uint2(b0h, b1h);
    fl[idx] = make_uint2(packlo_resid(b0h, W00, W01), packlo_resid(b1h, W08, W09));
}

// ---------------------------------------------------------------------------
// Exact bias term table: out[n,o] = sum_i feat[n,i] * b[i*32+o]
__global__ void k_bterm(const float* __restrict__ feat, const float* __restrict__ b,
                        float* __restrict__ out, int n) {
    int t = blockIdx.x * blockDim.x + threadIdx.x;
    if (t >= n * HD) return;
    int row = t >> 5, o = t & 31;
    float a = 0.f;
    #pragma unroll
    for (int i = 0; i < HD; i++)
        a = fmaf(feat[row * HD + i], b[i * HD + o], a);
    out[t] = a;
}

// ---------------------------------------------------------------------------
// NNConv via warp-level bf16 MMA with hi/lo split (3 MMAs per (i, nb)).
// One CTA = 8 warps = 128 edges; warp w owns rows 16w..16w+15.
__global__ void __launch_bounds__(256, 2)
k_nnconv_mma(const float* __restrict__ srcfeat, const float* __restrict__ efeat,
             const int* __restrict__ src, const int* __restrict__ dst,
             const uint2* __restrict__ gfh, const uint2* __restrict__ gfl,
             const float* __restrict__ bterm, float* __restrict__ acc) {
    extern __shared__ char smem[];
    float* nf_s = (float*)smem;
    uint2* fh_s = (uint2*)(smem + FH_OFF);
    uint2* fl_s = (uint2*)(smem + FL_OFF);
    int tid = threadIdx.x;
    int base = blockIdx.x * TILE_M;

    // copy B fragments (64 KB) into smem
    {
        const uint4* s1 = (const uint4*)gfh;
        const uint4* s2 = (const uint4*)gfl;
        uint4* d1 = (uint4*)fh_s;
        uint4* d2 = (uint4*)fl_s;
        #pragma unroll
        for (int q = 0; q < (NFRAG * 8 / 16) / 256; q++) {
            d1[q * 256 + tid] = s1[q * 256 + tid];
            d2[q * 256 + tid] = s2[q * 256 + tid];
        }
    }
    // gather nf rows (padded stride 33, conflict-free)
    for (int idx = tid; idx < TILE_M * HD; idx += 256) {
        int row = idx >> 5, col = idx & 31;
        int e = base + row;
        float v = 0.f;
        if (e < NEDGE) v = srcfeat[(size_t)src[e] * HD + col];
        nf_s[row * NF_STRIDE + col] = v;
    }
    __syncthreads();

    int lane = tid & 31, wid = tid >> 5;
    int r0 = lane >> 2, c0 = (lane & 3) * 2;
    int wr = wid * 16;
    int e0 = base + wr + r0;
    int e1 = e0 + 8;
    bool l0 = (e0 < NEDGE), l1 = (e1 < NEDGE);

    float pf0[4] = {0.f, 0.f, 0.f, 0.f}, pf1[4] = {0.f, 0.f, 0.f, 0.f};
    if (l0) {
        float2 t = *(const float2*)(efeat + (size_t)e0 * HE + c0);
        pf0[0] = t.x; pf0[1] = t.y;
        t = *(const float2*)(efeat + (size_t)e0 * HE + c0 + 8);
        pf0[2] = t.x; pf0[3] = t.y;
    }
    if (l1) {
        float2 t = *(const float2*)(efeat + (size_t)e1 * HE + c0);
        pf1[0] = t.x; pf1[1] = t.y;
        t = *(const float2*)(efeat + (size_t)e1 * HE + c0 + 8);
        pf1[2] = t.x; pf1[3] = t.y;
    }

    float d[4][4];
    #pragma unroll
    for (int nb = 0; nb < 4; nb++)
        #pragma unroll
        for (int q = 0; q < 4; q++) d[nb][q] = 0.f;

    #pragma unroll 4
    for (int i = 0; i < HD; i++) {
        float f0 = nf_s[(wr + r0) * NF_STRIDE + i];
        float f1 = nf_s[(wr + r0 + 8) * NF_STRIDE + i];
        float z00 = f0 * pf0[0], z01 = f0 * pf0[1], z02 = f0 * pf0[2], z03 = f0 * pf0[3];
        float z10 = f1 * pf1[0], z11 = f1 * pf1[1], z12 = f1 * pf1[2], z13 = f1 * pf1[3];
        u32 ah0 = bf16pair(z00, z01), ah1 = bf16pair(z10, z11);
        u32 ah2 = bf16pair(z02, z03), ah3 = bf16pair(z12, z13);
        u32 al0 = packlo_resid(ah0, z00, z01), al1 = packlo_resid(ah1, z10, z11);
        u32 al2 = packlo_resid(ah2, z02, z03), al3 = packlo_resid(ah3, z12, z13);
        #pragma unroll
        for (int nb = 0; nb < 4; nb++) {
            uint2 bh = fh_s[(i * 4 + nb) * 32 + lane];
            uint2 bl = fl_s[(i * 4 + nb) * 32 + lane];
            mma_bf16(d[nb], ah0, ah1, ah2, ah3, bh.x, bh.y);
            mma_bf16(d[nb], al0, al1, al2, al3, bh.x, bh.y);
            mma_bf16(d[nb], ah0, ah1, ah2, ah3, bl.x, bl.y);
        }
    }

    if (l0) {
        int s0 = src[e0], dn0 = dst[e0];
        const float* bt = bterm + (size_t)s0 * HD;
        float* ap = acc + (size_t)dn0 * HD;
        #pragma unroll
        for (int nb = 0; nb < 4; nb++) {
            int o = nb * 8 + c0;
            atomicAdd(ap + o,     d[nb][0] + bt[o]);
            atomicAdd(ap + o + 1, d[nb][1] + bt[o + 1]);
        }
    }
    if (l1) {
        int s1i = src[e1], dn1 = dst[e1];
        const float* bt = bterm + (size_t)s1i * HD;
        float* ap = acc + (size_t)dn1 * HD;
        #pragma unroll
        for (int nb = 0; nb < 4; nb++) {
            int o = nb * 8 + c0;
            atomicAdd(ap + o,     d[nb][2] + bt[o]);
            atomicAdd(ap + o + 1, d[nb][3] + bt[o + 1]);
        }
    }
}

// ---------------------------------------------------------------------------
__global__ void k_final(const float* __restrict__ pb, const float* __restrict__ nb,
                        float* __restrict__ out) {
    int t = blockIdx.x * blockDim.x + threadIdx.x;
    if (t >= N_NODE * HD) return;
    int n = t >> 5, o = t & 31;
    float p = g_accp[t] / fmaxf(g_deg_p[n], 1.f) + pb[o];
    float q = g_accn[t] / fmaxf(g_deg_n[n], 1.f) + nb[o];
    out[t] = fmaxf(p, q);
}

// ---------------------------------------------------------------------------
extern "C" void kernel_launch(void* const* d_in, const int* in_sizes, int n_in,
                              void* d_out, int out_size) {
    const float* node_feat = (const float*)d_in[0];
    const float* net_feat  = (const float*)d_in[1];
    const float* pin_feat  = (const float*)d_in[2];
    const float* edge_feat = (const float*)d_in[3];
    const float* topo_w    = (const float*)d_in[4];
    const float* topo_b    = (const float*)d_in[5];
    const float* geom_w    = (const float*)d_in[6];
    const float* geom_b    = (const float*)d_in[7];
    const float* gc_w      = (const float*)d_in[8];
    const float* gc_b      = (const float*)d_in[9];
    const float* pinned_b  = (const float*)d_in[10];
    const float* near_b    = (const float*)d_in[11];
    const int* pins_src    = (const int*)d_in[12];
    const int* pins_dst    = (const int*)d_in[13];
    const int* pinned_src  = (const int*)d_in[14];
    const int* pinned_dst  = (const int*)d_in[15];
    const int* near_src    = (const int*)d_in[16];
    const int* near_dst    = (const int*)d_in[17];
    float* out = (float*)d_out;

    cudaFuncSetAttribute(k_nnconv_mma, cudaFuncAttributeMaxDynamicSharedMemorySize, SM_TOT);

    float *accp, *accn, *btp, *btn;
    uint2 *fhp, *flp, *fhn, *fln;
    cudaGetSymbolAddress((void**)&accp, g_accp);
    cudaGetSymbolAddress((void**)&accn, g_accn);
    cudaGetSymbolAddress((void**)&btp,  g_btp);
    cudaGetSymbolAddress((void**)&btn,  g_btn);
    cudaGetSymbolAddress((void**)&fhp,  g_fh_p);
    cudaGetSymbolAddress((void**)&flp,  g_fl_p);
    cudaGetSymbolAddress((void**)&fhn,  g_fh_n);
    cudaGetSymbolAddress((void**)&fln,  g_fl_n);

    k_zero<<<512, 256>>>();
    k_deg<<<(NEDGE + 255) / 256, 256>>>(pins_src, pins_dst, pinned_dst, near_dst);
    k_pins<<<(NEDGE * HD + 255) / 256, 256>>>(node_feat, pins_src, pins_dst);
    k_netout<<<(N_NET * HD + 255) / 256, 256>>>(gc_w, gc_b, out);

    k_wprep<<<(NFRAG + 255) / 256, 256>>>(topo_w, fhp, flp);
    k_wprep<<<(NFRAG + 255) / 256, 256>>>(geom_w, fhn, fln);
    k_bterm<<<(N_NET  * HD + 255) / 256, 256>>>(net_feat,  topo_b, btp, N_NET);
    k_bterm<<<(N_NODE * HD + 255) / 256, 256>>>(node_feat, geom_b, btn, N_NODE);

    k_nnconv_mma<<<NTILES, 256, SM_TOT>>>(net_feat,  pin_feat,  pinned_src, pinned_dst,
                                          fhp, flp, btp, accp);
    k_nnconv_mma<<<NTILES, 256, SM_TOT>>>(node_feat, edge_feat, near_src,  near_dst,
                                          fhn, fln, btn, accn);

    k_final<<<(N_NODE * HD + 255) / 256, 256>>>(pinned_b, near_b, out);
}

// round 7
// speedup vs baseline: 3.1161x; 1.2868x over previous
#include <cuda_runtime.h>
#include <cuda_bf16.h>
#include <math.h>
#include <stdint.h>

#define N_NODE 80000
#define N_NET  20000
#define NEDGE  150000
#define HD     32
#define HE     16

#define TILE_M 128
#define NTILES ((NEDGE + TILE_M - 1) / TILE_M)   // 1172
#define TPC    2                                  // tiles per CTA
#define GRIDX  ((NTILES + TPC - 1) / TPC)         // 586
#define NFRAG  (HD * 4 * 32)                      // 4096 fragment slots (i, nb, lane)

// smem layout (bytes)
#define NF_STRIDE 33
#define NF_BYTES  (TILE_M * NF_STRIDE * 4)        // 16896 (16-aligned)
#define FH_OFF    NF_BYTES
#define FL_OFF    (NF_BYTES + NFRAG * 8)          // +32768
#define SM_TOT    (NF_BYTES + 2 * NFRAG * 8)      // 82432

typedef unsigned int u32;

// ---------------- helpers ----------------
__device__ __forceinline__ u32 bf16pair(float lo, float hi) {
    u32 r;  // cvt.rn.bf16x2.f32 d, a, b -> d = {hi=a, lo=b}
    asm("cvt.rn.bf16x2.f32 %0, %1, %2;" : "=r"(r) : "f"(hi), "f"(lo));
    return r;
}
__device__ __forceinline__ u32 packlo_resid(u32 h, float z0, float z1) {
    float r0 = z0 - __uint_as_float(h << 16);
    float r1 = z1 - __uint_as_float(h & 0xFFFF0000u);
    return bf16pair(r0, r1);
}
__device__ __forceinline__ void mma_bf16(float* d, u32 a0, u32 a1, u32 a2, u32 a3,
                                         u32 b0, u32 b1) {
    asm volatile(
        "mma.sync.aligned.m16n8k16.row.col.f32.bf16.bf16.f32 "
        "{%0,%1,%2,%3}, {%4,%5,%6,%7}, {%8,%9}, {%0,%1,%2,%3};"
        : "+f"(d[0]), "+f"(d[1]), "+f"(d[2]), "+f"(d[3])
        : "r"(a0), "r"(a1), "r"(a2), "r"(a3), "r"(b0), "r"(b1));
}
__device__ __forceinline__ void red_v2(float* p, float a, float b) {
    asm volatile("red.global.add.v2.f32 [%0], {%1, %2};"
                 :: "l"(p), "f"(a), "f"(b) : "memory");
}
__device__ __forceinline__ void red_v4(float* p, float a, float b, float c, float d) {
    asm volatile("red.global.add.v4.f32 [%0], {%1, %2, %3, %4};"
                 :: "l"(p), "f"(a), "f"(b), "f"(c), "f"(d) : "memory");
}

// ---- scratch (device globals; no allocation allowed) ----
__device__ float g_deg_out[N_NODE];
__device__ float g_deg_in [N_NET];
__device__ float g_deg_p  [N_NODE];
__device__ float g_deg_n  [N_NODE];
__device__ __align__(16) float g_agg [N_NET * HD];
__device__ __align__(16) float g_accp[N_NODE * HD];
__device__ __align__(16) float g_accn[N_NODE * HD];
__device__ float g_btp [N_NET  * HD];
__device__ float g_btn [N_NODE * HD];
__device__ __align__(16) uint2 g_fh_p[NFRAG];
__device__ __align__(16) uint2 g_fl_p[NFRAG];
__device__ __align__(16) uint2 g_fh_n[NFRAG];
__device__ __align__(16) uint2 g_fl_n[NFRAG];

// ---------------------------------------------------------------------------
__global__ void k_zero() {
    int stride = gridDim.x * blockDim.x;
    int i0 = blockIdx.x * blockDim.x + threadIdx.x;
    const float4 z = make_float4(0.f, 0.f, 0.f, 0.f);
    for (int j = i0; j < N_NODE / 4; j += stride) {
        reinterpret_cast<float4*>(g_deg_out)[j] = z;
        reinterpret_cast<float4*>(g_deg_p)[j] = z;
        reinterpret_cast<float4*>(g_deg_n)[j] = z;
    }
    for (int j = i0; j < N_NET / 4; j += stride) reinterpret_cast<float4*>(g_deg_in)[j] = z;
    for (int j = i0; j < N_NET * HD / 4; j += stride) reinterpret_cast<float4*>(g_agg)[j] = z;
    for (int j = i0; j < N_NODE * HD / 4; j += stride) {
        reinterpret_cast<float4*>(g_accp)[j] = z;
        reinterpret_cast<float4*>(g_accn)[j] = z;
    }
}

// ---------------------------------------------------------------------------
__global__ void k_deg(const int* __restrict__ ps, const int* __restrict__ pd,
                      const int* __restrict__ pnd, const int* __restrict__ nrd) {
    int e = blockIdx.x * blockDim.x + threadIdx.x;
    if (e >= NEDGE) return;
    atomicAdd(&g_deg_out[ps[e]],  1.f);
    atomicAdd(&g_deg_in [pd[e]],  1.f);
    atomicAdd(&g_deg_p  [pnd[e]], 1.f);
    atomicAdd(&g_deg_n  [nrd[e]], 1.f);
}

// ---------------------------------------------------------------------------
// pins aggregation with vector reductions: one thread per (edge, quarter-row)
__global__ void k_pins(const float* __restrict__ nodef,
                       const int* __restrict__ src, const int* __restrict__ dst) {
    int t = blockIdx.x * blockDim.x + threadIdx.x;
    if (t >= NEDGE * 8) return;
    int e = t >> 3, q = t & 7;
    int s = src[e];
    float nrm = rsqrtf(fmaxf(g_deg_out[s], 1.f));
    float4 v = reinterpret_cast<const float4*>(nodef + (size_t)s * HD)[q];
    red_v4(g_agg + (size_t)dst[e] * HD + q * 4,
           v.x * nrm, v.y * nrm, v.z * nrm, v.w * nrm);
}

// ---------------------------------------------------------------------------
__global__ void k_netout(const float* __restrict__ gcw, const float* __restrict__ gcb,
                         float* __restrict__ out) {
    int t = blockIdx.x * blockDim.x + threadIdx.x;
    if (t >= N_NET * HD) return;
    int n = t >> 5, o = t & 31;
    float nrm = rsqrtf(fmaxf(g_deg_in[n], 1.f));
    float a = 0.f;
    #pragma unroll
    for (int d = 0; d < HD; d++)
        a = fmaf(g_agg[n * HD + d], gcw[d * HD + o], a);
    out[(size_t)N_NODE * HD + t] = a * nrm + gcb[o];
}

// ---------------------------------------------------------------------------
// Precompute B fragments for BOTH relations (hi/lo split, m16n8k16 .col layout).
__global__ void k_wprep(const float* __restrict__ w0, const float* __restrict__ w1,
                        uint2* __restrict__ fh0, uint2* __restrict__ fl0,
                        uint2* __restrict__ fh1, uint2* __restrict__ fl1) {
    int gidx = blockIdx.x * blockDim.x + threadIdx.x;
    if (gidx >= 2 * NFRAG) return;
    int rel = gidx >= NFRAG;
    int idx = gidx - rel * NFRAG;
    const float* w = rel ? w1 : w0;
    uint2* fh = rel ? fh1 : fh0;
    uint2* fl = rel ? fl1 : fl0;
    int lane = idx & 31, nb = (idx >> 5) & 3, i = idx >> 7;
    int o = nb * 8 + (lane >> 2);
    int k0 = (lane & 3) * 2;
    const float* row = w + ((size_t)i * HD + o) * HE;
    float W00 = row[k0],     W01 = row[k0 + 1];
    float W08 = row[k0 + 8], W09 = row[k0 + 9];
    u32 b0h = bf16pair(W00, W01);
    u32 b1h = bf16pair(W08, W09);
    fh[idx] = make_uint2(b0h, b1h);
    fl[idx] = make_uint2(packlo_resid(b0h, W00, W01), packlo_resid(b1h, W08, W09));
}

// ---------------------------------------------------------------------------
// Exact bias term tables for both relations in one launch.
__global__ void k_bterm(const float* __restrict__ netf, const float* __restrict__ tb,
                        const float* __restrict__ nodef, const float* __restrict__ gb) {
    int t = blockIdx.x * blockDim.x + threadIdx.x;
    if (t >= (N_NET + N_NODE) * HD) return;
    const float* feat; const float* b; float* out; int row;
    if (t < N_NET * HD) {
        feat = netf; b = tb; out = g_btp; row = t >> 5;
    } else {
        t -= N_NET * HD;
        feat = nodef; b = gb; out = g_btn; row = t >> 5;
    }
    int o = t & 31;
    float a = 0.f;
    #pragma unroll
    for (int i = 0; i < HD; i++)
        a = fmaf(feat[(size_t)row * HD + i], b[i * HD + o], a);
    out[(size_t)row * HD + o] = a;
}

// ---------------------------------------------------------------------------
// Fused NNConv: blockIdx.y selects relation, TPC tiles per CTA (fragment copy reused).
__global__ void __launch_bounds__(256, 2)
k_nnconv_mma(const float* __restrict__ sf0, const float* __restrict__ ef0,
             const int* __restrict__ src0, const int* __restrict__ dst0,
             const uint2* __restrict__ gfh0, const uint2* __restrict__ gfl0,
             const float* __restrict__ bt0, float* __restrict__ acc0,
             const float* __restrict__ sf1, const float* __restrict__ ef1,
             const int* __restrict__ src1, const int* __restrict__ dst1,
             const uint2* __restrict__ gfh1, const uint2* __restrict__ gfl1,
             const float* __restrict__ bt1, float* __restrict__ acc1) {
    extern __shared__ char smem[];
    float* nf_s = (float*)smem;
    uint2* fh_s = (uint2*)(smem + FH_OFF);
    uint2* fl_s = (uint2*)(smem + FL_OFF);
    int tid = threadIdx.x;
    int rel = blockIdx.y;

    const float* srcfeat = rel ? sf1 : sf0;
    const float* efeat   = rel ? ef1 : ef0;
    const int* src       = rel ? src1 : src0;
    const int* dst       = rel ? dst1 : dst0;
    const uint2* gfh     = rel ? gfh1 : gfh0;
    const uint2* gfl     = rel ? gfl1 : gfl0;
    const float* bterm   = rel ? bt1 : bt0;
    float* acc           = rel ? acc1 : acc0;

    // copy B fragments (64 KB) into smem once
    {
        const uint4* s1 = (const uint4*)gfh;
        const uint4* s2 = (const uint4*)gfl;
        uint4* d1 = (uint4*)fh_s;
        uint4* d2 = (uint4*)fl_s;
        #pragma unroll
        for (int q = 0; q < (NFRAG * 8 / 16) / 256; q++) {
            d1[q * 256 + tid] = s1[q * 256 + tid];
            d2[q * 256 + tid] = s2[q * 256 + tid];
        }
    }

    int lane = tid & 31, wid = tid >> 5;
    int r0 = lane >> 2, c0 = (lane & 3) * 2;
    int wr = wid * 16;

    #pragma unroll 1
    for (int t = 0; t < TPC; t++) {
        int tile = blockIdx.x * TPC + t;
        if (tile >= NTILES) break;
        int base = tile * TILE_M;

        __syncthreads();   // protect nf_s reuse (and fragment copy on t=0)
        for (int idx = tid; idx < TILE_M * HD; idx += 256) {
            int row = idx >> 5, col = idx & 31;
            int e = base + row;
            float v = 0.f;
            if (e < NEDGE) v = srcfeat[(size_t)src[e] * HD + col];
            nf_s[row * NF_STRIDE + col] = v;
        }
        __syncthreads();

        int e0 = base + wr + r0;
        int e1 = e0 + 8;
        bool l0 = (e0 < NEDGE), l1 = (e1 < NEDGE);

        float pf0[4] = {0.f, 0.f, 0.f, 0.f}, pf1[4] = {0.f, 0.f, 0.f, 0.f};
        if (l0) {
            float2 q = *(const float2*)(efeat + (size_t)e0 * HE + c0);
            pf0[0] = q.x; pf0[1] = q.y;
            q = *(const float2*)(efeat + (size_t)e0 * HE + c0 + 8);
            pf0[2] = q.x; pf0[3] = q.y;
        }
        if (l1) {
            float2 q = *(const float2*)(efeat + (size_t)e1 * HE + c0);
            pf1[0] = q.x; pf1[1] = q.y;
            q = *(const float2*)(efeat + (size_t)e1 * HE + c0 + 8);
            pf1[2] = q.x; pf1[3] = q.y;
        }

        float d[4][4];
        #pragma unroll
        for (int nb = 0; nb < 4; nb++)
            #pragma unroll
            for (int q = 0; q < 4; q++) d[nb][q] = 0.f;

        #pragma unroll 4
        for (int i = 0; i < HD; i++) {
            float f0 = nf_s[(wr + r0) * NF_STRIDE + i];
            float f1 = nf_s[(wr + r0 + 8) * NF_STRIDE + i];
            float z00 = f0 * pf0[0], z01 = f0 * pf0[1], z02 = f0 * pf0[2], z03 = f0 * pf0[3];
            float z10 = f1 * pf1[0], z11 = f1 * pf1[1], z12 = f1 * pf1[2], z13 = f1 * pf1[3];
            u32 ah0 = bf16pair(z00, z01), ah1 = bf16pair(z10, z11);
            u32 ah2 = bf16pair(z02, z03), ah3 = bf16pair(z12, z13);
            u32 al0 = packlo_resid(ah0, z00, z01), al1 = packlo_resid(ah1, z10, z11);
            u32 al2 = packlo_resid(ah2, z02, z03), al3 = packlo_resid(ah3, z12, z13);
            #pragma unroll
            for (int nb = 0; nb < 4; nb++) {
                uint2 bh = fh_s[(i * 4 + nb) * 32 + lane];
                uint2 bl = fl_s[(i * 4 + nb) * 32 + lane];
                mma_bf16(d[nb], ah0, ah1, ah2, ah3, bh.x, bh.y);
                mma_bf16(d[nb], al0, al1, al2, al3, bh.x, bh.y);
                mma_bf16(d[nb], ah0, ah1, ah2, ah3, bl.x, bl.y);
            }
        }

        if (l0) {
            int s0 = src[e0], dn0 = dst[e0];
            const float* bt = bterm + (size_t)s0 * HD;
            float* ap = acc + (size_t)dn0 * HD;
            #pragma unroll
            for (int nb = 0; nb < 4; nb++) {
                int o = nb * 8 + c0;
                red_v2(ap + o, d[nb][0] + bt[o], d[nb][1] + bt[o + 1]);
            }
        }
        if (l1) {
            int s1i = src[e1], dn1 = dst[e1];
            const float* bt = bterm + (size_t)s1i * HD;
            float* ap = acc + (size_t)dn1 * HD;
            #pragma unroll
            for (int nb = 0; nb < 4; nb++) {
                int o = nb * 8 + c0;
                red_v2(ap + o, d[nb][2] + bt[o], d[nb][3] + bt[o + 1]);
            }
        }
    }
}

// ---------------------------------------------------------------------------
__global__ void k_final(const float* __restrict__ pb, const float* __restrict__ nb,
                        float* __restrict__ out) {
    int t = blockIdx.x * blockDim.x + threadIdx.x;
    if (t >= N_NODE * HD) return;
    int n = t >> 5, o = t & 31;
    float p = g_accp[t] / fmaxf(g_deg_p[n], 1.f) + pb[o];
    float q = g_accn[t] / fmaxf(g_deg_n[n], 1.f) + nb[o];
    out[t] = fmaxf(p, q);
}

// ---------------------------------------------------------------------------
extern "C" void kernel_launch(void* const* d_in, const int* in_sizes, int n_in,
                              void* d_out, int out_size) {
    const float* node_feat = (const float*)d_in[0];
    const float* net_feat  = (const float*)d_in[1];
    const float* pin_feat  = (const float*)d_in[2];
    const float* edge_feat = (const float*)d_in[3];
    const float* topo_w    = (const float*)d_in[4];
    const float* topo_b    = (const float*)d_in[5];
    const float* geom_w    = (const float*)d_in[6];
    const float* geom_b    = (const float*)d_in[7];
    const float* gc_w      = (const float*)d_in[8];
    const float* gc_b      = (const float*)d_in[9];
    const float* pinned_b  = (const float*)d_in[10];
    const float* near_b    = (const float*)d_in[11];
    const int* pins_src    = (const int*)d_in[12];
    const int* pins_dst    = (const int*)d_in[13];
    const int* pinned_src  = (const int*)d_in[14];
    const int* pinned_dst  = (const int*)d_in[15];
    const int* near_src    = (const int*)d_in[16];
    const int* near_dst    = (const int*)d_in[17];
    float* out = (float*)d_out;

    cudaFuncSetAttribute(k_nnconv_mma, cudaFuncAttributeMaxDynamicSharedMemorySize, SM_TOT);

    float *accp, *accn, *btp, *btn;
    uint2 *fhp, *flp, *fhn, *fln;
    cudaGetSymbolAddress((void**)&accp, g_accp);
    cudaGetSymbolAddress((void**)&accn, g_accn);
    cudaGetSymbolAddress((void**)&btp,  g_btp);
    cudaGetSymbolAddress((void**)&btn,  g_btn);
    cudaGetSymbolAddress((void**)&fhp,  g_fh_p);
    cudaGetSymbolAddress((void**)&flp,  g_fl_p);
    cudaGetSymbolAddress((void**)&fhn,  g_fh_n);
    cudaGetSymbolAddress((void**)&fln,  g_fl_n);

    k_zero<<<512, 256>>>();
    k_deg<<<(NEDGE + 255) / 256, 256>>>(pins_src, pins_dst, pinned_dst, near_dst);
    k_pins<<<(NEDGE * 8 + 255) / 256, 256>>>(node_feat, pins_src, pins_dst);
    k_netout<<<(N_NET * HD + 255) / 256, 256>>>(gc_w, gc_b, out);

    k_wprep<<<(2 * NFRAG + 255) / 256, 256>>>(topo_w, geom_w, fhp, flp, fhn, fln);
    k_bterm<<<((N_NET + N_NODE) * HD + 255) / 256, 256>>>(net_feat, topo_b,
                                                          node_feat, geom_b);

    dim3 grid(GRIDX, 2);
    k_nnconv_mma<<<grid, 256, SM_TOT>>>(net_feat,  pin_feat,  pinned_src, pinned_dst,
                                        fhp, flp, btp, accp,
                                        node_feat, edge_feat, near_src,  near_dst,
                                        fhn, fln, btn, accn);

    k_final<<<(N_NODE * HD + 255) / 256, 256>>>(pinned_b, near_b, out);
}

// round 8
// speedup vs baseline: 3.2750x; 1.0510x over previous
#include <cuda_runtime.h>
#include <cuda_bf16.h>
#include <math.h>
#include <stdint.h>

#define N_NODE 80000
#define N_NET  20000
#define NEDGE  150000
#define HD     32
#define HE     16

#define TILE_M 128
#define NTILES ((NEDGE + TILE_M - 1) / TILE_M)   // 1172
#define TPC    4                                  // tiles per CTA
#define GRIDX  ((NTILES + TPC - 1) / TPC)         // 293
#define NFRAG  (HD * 4 * 32)                      // 4096 fragment slots (i, nb, lane)

// smem layout (bytes)
#define NF_STRIDE 33
#define NF_BYTES  (TILE_M * NF_STRIDE * 4)        // 16896 (16-aligned)
#define FH_OFF    NF_BYTES
#define FL_OFF    (NF_BYTES + NFRAG * 8)          // +32768
#define SM_TOT    (NF_BYTES + 2 * NFRAG * 8)      // 82432

typedef unsigned int u32;

// ---------------- helpers ----------------
__device__ __forceinline__ u32 bf16pair(float lo, float hi) {
    u32 r;  // cvt.rn.bf16x2.f32 d, a, b -> d = {hi=a, lo=b}
    asm("cvt.rn.bf16x2.f32 %0, %1, %2;" : "=r"(r) : "f"(hi), "f"(lo));
    return r;
}
__device__ __forceinline__ u32 packlo_resid(u32 h, float z0, float z1) {
    float r0 = z0 - __uint_as_float(h << 16);
    float r1 = z1 - __uint_as_float(h & 0xFFFF0000u);
    return bf16pair(r0, r1);
}
__device__ __forceinline__ void mma_bf16(float* d, u32 a0, u32 a1, u32 a2, u32 a3,
                                         u32 b0, u32 b1) {
    asm volatile(
        "mma.sync.aligned.m16n8k16.row.col.f32.bf16.bf16.f32 "
        "{%0,%1,%2,%3}, {%4,%5,%6,%7}, {%8,%9}, {%0,%1,%2,%3};"
        : "+f"(d[0]), "+f"(d[1]), "+f"(d[2]), "+f"(d[3])
        : "r"(a0), "r"(a1), "r"(a2), "r"(a3), "r"(b0), "r"(b1));
}
__device__ __forceinline__ void red_v2(float* p, float a, float b) {
    asm volatile("red.global.add.v2.f32 [%0], {%1, %2};"
                 :: "l"(p), "f"(a), "f"(b) : "memory");
}
__device__ __forceinline__ void red_v4(float* p, float a, float b, float c, float d) {
    asm volatile("red.global.add.v4.f32 [%0], {%1, %2, %3, %4};"
                 :: "l"(p), "f"(a), "f"(b), "f"(c), "f"(d) : "memory");
}

// ---- scratch (device globals; no allocation allowed) ----
__device__ float g_deg_out[N_NODE];
__device__ float g_deg_in [N_NET];
__device__ float g_deg_p  [N_NODE];
__device__ float g_deg_n  [N_NODE];
__device__ __align__(16) float g_agg [N_NET * HD];
__device__ __align__(16) float g_accp[N_NODE * HD];
__device__ __align__(16) float g_accn[N_NODE * HD];
__device__ float g_btp [N_NET  * HD];
__device__ float g_btn [N_NODE * HD];
__device__ __align__(16) uint2 g_fh_p[NFRAG];
__device__ __align__(16) uint2 g_fl_p[NFRAG];
__device__ __align__(16) uint2 g_fh_n[NFRAG];
__device__ __align__(16) uint2 g_fl_n[NFRAG];

// ---------------------------------------------------------------------------
__global__ void k_zero() {
    int stride = gridDim.x * blockDim.x;
    int i0 = blockIdx.x * blockDim.x + threadIdx.x;
    const float4 z = make_float4(0.f, 0.f, 0.f, 0.f);
    for (int j = i0; j < N_NODE / 4; j += stride) {
        reinterpret_cast<float4*>(g_deg_out)[j] = z;
        reinterpret_cast<float4*>(g_deg_p)[j] = z;
        reinterpret_cast<float4*>(g_deg_n)[j] = z;
    }
    for (int j = i0; j < N_NET / 4; j += stride) reinterpret_cast<float4*>(g_deg_in)[j] = z;
    for (int j = i0; j < N_NET * HD / 4; j += stride) reinterpret_cast<float4*>(g_agg)[j] = z;
    for (int j = i0; j < N_NODE * HD / 4; j += stride) {
        reinterpret_cast<float4*>(g_accp)[j] = z;
        reinterpret_cast<float4*>(g_accn)[j] = z;
    }
}

// ---------------------------------------------------------------------------
__global__ void k_deg(const int* __restrict__ ps, const int* __restrict__ pd,
                      const int* __restrict__ pnd, const int* __restrict__ nrd) {
    int e = blockIdx.x * blockDim.x + threadIdx.x;
    if (e >= NEDGE) return;
    atomicAdd(&g_deg_out[ps[e]],  1.f);
    atomicAdd(&g_deg_in [pd[e]],  1.f);
    atomicAdd(&g_deg_p  [pnd[e]], 1.f);
    atomicAdd(&g_deg_n  [nrd[e]], 1.f);
}

// ---------------------------------------------------------------------------
// pins aggregation with vector reductions: one thread per (edge, quarter-row)
__global__ void k_pins(const float* __restrict__ nodef,
                       const int* __restrict__ src, const int* __restrict__ dst) {
    int t = blockIdx.x * blockDim.x + threadIdx.x;
    if (t >= NEDGE * 8) return;
    int e = t >> 3, q = t & 7;
    int s = src[e];
    float nrm = rsqrtf(fmaxf(g_deg_out[s], 1.f));
    float4 v = reinterpret_cast<const float4*>(nodef + (size_t)s * HD)[q];
    red_v4(g_agg + (size_t)dst[e] * HD + q * 4,
           v.x * nrm, v.y * nrm, v.z * nrm, v.w * nrm);
}

// ---------------------------------------------------------------------------
__global__ void k_netout(const float* __restrict__ gcw, const float* __restrict__ gcb,
                         float* __restrict__ out) {
    int t = blockIdx.x * blockDim.x + threadIdx.x;
    if (t >= N_NET * HD) return;
    int n = t >> 5, o = t & 31;
    float nrm = rsqrtf(fmaxf(g_deg_in[n], 1.f));
    float a = 0.f;
    #pragma unroll
    for (int d = 0; d < HD; d++)
        a = fmaf(g_agg[n * HD + d], gcw[d * HD + o], a);
    out[(size_t)N_NODE * HD + t] = a * nrm + gcb[o];
}

// ---------------------------------------------------------------------------
// Precompute B fragments for BOTH relations (hi/lo split, m16n8k16 .col layout).
__global__ void k_wprep(const float* __restrict__ w0, const float* __restrict__ w1,
                        uint2* __restrict__ fh0, uint2* __restrict__ fl0,
                        uint2* __restrict__ fh1, uint2* __restrict__ fl1) {
    int gidx = blockIdx.x * blockDim.x + threadIdx.x;
    if (gidx >= 2 * NFRAG) return;
    int rel = gidx >= NFRAG;
    int idx = gidx - rel * NFRAG;
    const float* w = rel ? w1 : w0;
    uint2* fh = rel ? fh1 : fh0;
    uint2* fl = rel ? fl1 : fl0;
    int lane = idx & 31, nb = (idx >> 5) & 3, i = idx >> 7;
    int o = nb * 8 + (lane >> 2);
    int k0 = (lane & 3) * 2;
    const float* row = w + ((size_t)i * HD + o) * HE;
    float W00 = row[k0],     W01 = row[k0 + 1];
    float W08 = row[k0 + 8], W09 = row[k0 + 9];
    u32 b0h = bf16pair(W00, W01);
    u32 b1h = bf16pair(W08, W09);
    fh[idx] = make_uint2(b0h, b1h);
    fl[idx] = make_uint2(packlo_resid(b0h, W00, W01), packlo_resid(b1h, W08, W09));
}

// ---------------------------------------------------------------------------
// Exact bias term tables for both relations in one launch.
__global__ void k_bterm(const float* __restrict__ netf, const float* __restrict__ tb,
                        const float* __restrict__ nodef, const float* __restrict__ gb) {
    int t = blockIdx.x * blockDim.x + threadIdx.x;
    if (t >= (N_NET + N_NODE) * HD) return;
    const float* feat; const float* b; float* out; int row;
    if (t < N_NET * HD) {
        feat = netf; b = tb; out = g_btp; row = t >> 5;
    } else {
        t -= N_NET * HD;
        feat = nodef; b = gb; out = g_btn; row = t >> 5;
    }
    int o = t & 31;
    float a = 0.f;
    #pragma unroll
    for (int i = 0; i < HD; i++)
        a = fmaf(feat[(size_t)row * HD + i], b[i * HD + o], a);
    out[(size_t)row * HD + o] = a;
}

// ---------------------------------------------------------------------------
// Fused NNConv: blockIdx.y selects relation, TPC tiles per CTA (fragment copy reused).
__global__ void __launch_bounds__(256, 2)
k_nnconv_mma(const float* __restrict__ sf0, const float* __restrict__ ef0,
             const int* __restrict__ src0, const int* __restrict__ dst0,
             const uint2* __restrict__ gfh0, const uint2* __restrict__ gfl0,
             const float* __restrict__ bt0, float* __restrict__ acc0,
             const float* __restrict__ sf1, const float* __restrict__ ef1,
             const int* __restrict__ src1, const int* __restrict__ dst1,
             const uint2* __restrict__ gfh1, const uint2* __restrict__ gfl1,
             const float* __restrict__ bt1, float* __restrict__ acc1) {
    extern __shared__ char smem[];
    float* nf_s = (float*)smem;
    uint2* fh_s = (uint2*)(smem + FH_OFF);
    uint2* fl_s = (uint2*)(smem + FL_OFF);
    int tid = threadIdx.x;
    int rel = blockIdx.y;

    const float* srcfeat = rel ? sf1 : sf0;
    const float* efeat   = rel ? ef1 : ef0;
    const int* src       = rel ? src1 : src0;
    const int* dst       = rel ? dst1 : dst0;
    const uint2* gfh     = rel ? gfh1 : gfh0;
    const uint2* gfl     = rel ? gfl1 : gfl0;
    const float* bterm   = rel ? bt1 : bt0;
    float* acc           = rel ? acc1 : acc0;

    // copy B fragments (64 KB) into smem once
    {
        const uint4* s1 = (const uint4*)gfh;
        const uint4* s2 = (const uint4*)gfl;
        uint4* d1 = (uint4*)fh_s;
        uint4* d2 = (uint4*)fl_s;
        #pragma unroll
        for (int q = 0; q < (NFRAG * 8 / 16) / 256; q++) {
            d1[q * 256 + tid] = s1[q * 256 + tid];
            d2[q * 256 + tid] = s2[q * 256 + tid];
        }
    }

    int lane = tid & 31, wid = tid >> 5;
    int r0 = lane >> 2, c0 = (lane & 3) * 2;
    int wr = wid * 16;

    #pragma unroll 1
    for (int t = 0; t < TPC; t++) {
        int tile = blockIdx.x * TPC + t;
        if (tile >= NTILES) break;
        int base = tile * TILE_M;

        __syncthreads();   // protect nf_s reuse (and fragment copy on t=0)
        for (int idx = tid; idx < TILE_M * HD; idx += 256) {
            int row = idx >> 5, col = idx & 31;
            int e = base + row;
            float v = 0.f;
            if (e < NEDGE) v = srcfeat[(size_t)src[e] * HD + col];
            nf_s[row * NF_STRIDE + col] = v;
        }
        __syncthreads();

        int e0 = base + wr + r0;
        int e1 = e0 + 8;
        bool l0 = (e0 < NEDGE), l1 = (e1 < NEDGE);

        float pf0[4] = {0.f, 0.f, 0.f, 0.f}, pf1[4] = {0.f, 0.f, 0.f, 0.f};
        if (l0) {
            float2 q = *(const float2*)(efeat + (size_t)e0 * HE + c0);
            pf0[0] = q.x; pf0[1] = q.y;
            q = *(const float2*)(efeat + (size_t)e0 * HE + c0 + 8);
            pf0[2] = q.x; pf0[3] = q.y;
        }
        if (l1) {
            float2 q = *(const float2*)(efeat + (size_t)e1 * HE + c0);
            pf1[0] = q.x; pf1[1] = q.y;
            q = *(const float2*)(efeat + (size_t)e1 * HE + c0 + 8);
            pf1[2] = q.x; pf1[3] = q.y;
        }

        float d[4][4];
        #pragma unroll
        for (int nb = 0; nb < 4; nb++)
            #pragma unroll
            for (int q = 0; q < 4; q++) d[nb][q] = 0.f;

        #pragma unroll 4
        for (int i = 0; i < HD; i++) {
            float f0 = nf_s[(wr + r0) * NF_STRIDE + i];
            float f1 = nf_s[(wr + r0 + 8) * NF_STRIDE + i];
            float z00 = f0 * pf0[0], z01 = f0 * pf0[1], z02 = f0 * pf0[2], z03 = f0 * pf0[3];
            float z10 = f1 * pf1[0], z11 = f1 * pf1[1], z12 = f1 * pf1[2], z13 = f1 * pf1[3];
            u32 ah0 = bf16pair(z00, z01), ah1 = bf16pair(z10, z11);
            u32 ah2 = bf16pair(z02, z03), ah3 = bf16pair(z12, z13);
            u32 al0 = packlo_resid(ah0, z00, z01), al1 = packlo_resid(ah1, z10, z11);
            u32 al2 = packlo_resid(ah2, z02, z03), al3 = packlo_resid(ah3, z12, z13);
            #pragma unroll
            for (int nb = 0; nb < 4; nb++) {
                uint2 bh = fh_s[(i * 4 + nb) * 32 + lane];
                uint2 bl = fl_s[(i * 4 + nb) * 32 + lane];
                mma_bf16(d[nb], ah0, ah1, ah2, ah3, bh.x, bh.y);
                mma_bf16(d[nb], al0, al1, al2, al3, bh.x, bh.y);
                mma_bf16(d[nb], ah0, ah1, ah2, ah3, bl.x, bl.y);
            }
        }

        if (l0) {
            int s0 = src[e0], dn0 = dst[e0];
            const float* bt = bterm + (size_t)s0 * HD;
            float* ap = acc + (size_t)dn0 * HD;
            #pragma unroll
            for (int nb = 0; nb < 4; nb++) {
                int o = nb * 8 + c0;
                red_v2(ap + o, d[nb][0] + bt[o], d[nb][1] + bt[o + 1]);
            }
        }
        if (l1) {
            int s1i = src[e1], dn1 = dst[e1];
            const float* bt = bterm + (size_t)s1i * HD;
            float* ap = acc + (size_t)dn1 * HD;
            #pragma unroll
            for (int nb = 0; nb < 4; nb++) {
                int o = nb * 8 + c0;
                red_v2(ap + o, d[nb][2] + bt[o], d[nb][3] + bt[o + 1]);
            }
        }
    }
}

// ---------------------------------------------------------------------------
__global__ void k_final(const float* __restrict__ pb, const float* __restrict__ nb,
                        float* __restrict__ out) {
    int t = blockIdx.x * blockDim.x + threadIdx.x;
    if (t >= N_NODE * HD) return;
    int n = t >> 5, o = t & 31;
    float p = g_accp[t] / fmaxf(g_deg_p[n], 1.f) + pb[o];
    float q = g_accn[t] / fmaxf(g_deg_n[n], 1.f) + nb[o];
    out[t] = fmaxf(p, q);
}

// ---------------------------------------------------------------------------
extern "C" void kernel_launch(void* const* d_in, const int* in_sizes, int n_in,
                              void* d_out, int out_size) {
    const float* node_feat = (const float*)d_in[0];
    const float* net_feat  = (const float*)d_in[1];
    const float* pin_feat  = (const float*)d_in[2];
    const float* edge_feat = (const float*)d_in[3];
    const float* topo_w    = (const float*)d_in[4];
    const float* topo_b    = (const float*)d_in[5];
    const float* geom_w    = (const float*)d_in[6];
    const float* geom_b    = (const float*)d_in[7];
    const float* gc_w      = (const float*)d_in[8];
    const float* gc_b      = (const float*)d_in[9];
    const float* pinned_b  = (const float*)d_in[10];
    const float* near_b    = (const float*)d_in[11];
    const int* pins_src    = (const int*)d_in[12];
    const int* pins_dst    = (const int*)d_in[13];
    const int* pinned_src  = (const int*)d_in[14];
    const int* pinned_dst  = (const int*)d_in[15];
    const int* near_src    = (const int*)d_in[16];
    const int* near_dst    = (const int*)d_in[17];
    float* out = (float*)d_out;

    cudaFuncSetAttribute(k_nnconv_mma, cudaFuncAttributeMaxDynamicSharedMemorySize, SM_TOT);

    float *accp, *accn, *btp, *btn;
    uint2 *fhp, *flp, *fhn, *fln;
    cudaGetSymbolAddress((void**)&accp, g_accp);
    cudaGetSymbolAddress((void**)&accn, g_accn);
    cudaGetSymbolAddress((void**)&btp,  g_btp);
    cudaGetSymbolAddress((void**)&btn,  g_btn);
    cudaGetSymbolAddress((void**)&fhp,  g_fh_p);
    cudaGetSymbolAddress((void**)&flp,  g_fl_p);
    cudaGetSymbolAddress((void**)&fhn,  g_fh_n);
    cudaGetSymbolAddress((void**)&fln,  g_fl_n);

    // Fork-join concurrency: side stream runs the pins-relation chain while the
    // origin (legacy default) stream runs the NNConv chain. Capturable pattern:
    // event-record on origin -> wait on side stream (fork), event joins back.
    cudaStream_t s2;
    cudaStreamCreateWithFlags(&s2, cudaStreamNonBlocking);
    cudaEvent_t evFork, evZero, evDeg, evJoin;
    cudaEventCreateWithFlags(&evFork, cudaEventDisableTiming);
    cudaEventCreateWithFlags(&evZero, cudaEventDisableTiming);
    cudaEventCreateWithFlags(&evDeg,  cudaEventDisableTiming);
    cudaEventCreateWithFlags(&evJoin, cudaEventDisableTiming);

    cudaEventRecord(evFork, 0);
    cudaStreamWaitEvent(s2, evFork, 0);

    // --- side stream: zero + degrees + pins relation ---
    k_zero<<<512, 256, 0, s2>>>();
    cudaEventRecord(evZero, s2);
    k_deg<<<(NEDGE + 255) / 256, 256, 0, s2>>>(pins_src, pins_dst, pinned_dst, near_dst);
    cudaEventRecord(evDeg, s2);
    k_pins<<<(NEDGE * 8 + 255) / 256, 256, 0, s2>>>(node_feat, pins_src, pins_dst);
    k_netout<<<(N_NET * HD + 255) / 256, 256, 0, s2>>>(gc_w, gc_b, out);
    cudaEventRecord(evJoin, s2);

    // --- origin stream: fragment/bias prep + NNConv + final ---
    k_wprep<<<(2 * NFRAG + 255) / 256, 256>>>(topo_w, geom_w, fhp, flp, fhn, fln);
    k_bterm<<<((N_NET + N_NODE) * HD + 255) / 256, 256>>>(net_feat, topo_b,
                                                          node_feat, geom_b);
    cudaStreamWaitEvent(0, evZero, 0);   // acc buffers zeroed
    dim3 grid(GRIDX, 2);
    k_nnconv_mma<<<grid, 256, SM_TOT>>>(net_feat,  pin_feat,  pinned_src, pinned_dst,
                                        fhp, flp, btp, accp,
                                        node_feat, edge_feat, near_src,  near_dst,
                                        fhn, fln, btn, accn);
    cudaStreamWaitEvent(0, evDeg, 0);    // g_deg_p / g_deg_n ready
    k_final<<<(N_NODE * HD + 255) / 256, 256>>>(pinned_b, near_b, out);
    cudaStreamWaitEvent(0, evJoin, 0);   // join side stream (net_out part of out)
}

// round 9
// speedup vs baseline: 3.7196x; 1.1358x over previous
#include <cuda_runtime.h>
#include <cuda_fp16.h>
#include <math.h>
#include <stdint.h>

#define N_NODE 80000
#define N_NET  20000
#define NEDGE  150000
#define HD     32
#define HE     16

#define TILE_M 128
#define NTILES ((NEDGE + TILE_M - 1) / TILE_M)   // 1172
#define TPC    4                                  // tiles per CTA
#define GRIDX  ((NTILES + TPC - 1) / TPC)         // 293
#define NFRAG  (HD * 4 * 32)                      // 4096 fragment slots (i, nb, lane)

// smem layout (bytes)
#define NF_STRIDE 33
#define NF_BYTES  (TILE_M * NF_STRIDE * 4)        // 16896 (16-aligned)
#define FH_OFF    NF_BYTES
#define SM_TOT    (NF_BYTES + NFRAG * 8)          // 49664

typedef unsigned int u32;

// ---------------- helpers ----------------
__device__ __forceinline__ u32 f16pair(float lo, float hi) {
    __half2 h = __floats2half2_rn(lo, hi);        // x=lo, y=hi
    return *reinterpret_cast<u32*>(&h);
}
__device__ __forceinline__ void mma_f16(float* d, u32 a0, u32 a1, u32 a2, u32 a3,
                                        u32 b0, u32 b1) {
    asm volatile(
        "mma.sync.aligned.m16n8k16.row.col.f32.f16.f16.f32 "
        "{%0,%1,%2,%3}, {%4,%5,%6,%7}, {%8,%9}, {%0,%1,%2,%3};"
        : "+f"(d[0]), "+f"(d[1]), "+f"(d[2]), "+f"(d[3])
        : "r"(a0), "r"(a1), "r"(a2), "r"(a3), "r"(b0), "r"(b1));
}
__device__ __forceinline__ void red_v2(float* p, float a, float b) {
    asm volatile("red.global.add.v2.f32 [%0], {%1, %2};"
                 :: "l"(p), "f"(a), "f"(b) : "memory");
}
__device__ __forceinline__ void red_v4(float* p, float a, float b, float c, float d) {
    asm volatile("red.global.add.v4.f32 [%0], {%1, %2, %3, %4};"
                 :: "l"(p), "f"(a), "f"(b), "f"(c), "f"(d) : "memory");
}

// ---- scratch (device globals; no allocation allowed) ----
__device__ float g_deg_out[N_NODE];
__device__ float g_deg_in [N_NET];
__device__ float g_deg_p  [N_NODE];
__device__ float g_deg_n  [N_NODE];
__device__ __align__(16) float g_agg [N_NET * HD];
__device__ __align__(16) float g_accp[N_NODE * HD];
__device__ __align__(16) float g_accn[N_NODE * HD];
__device__ float g_btp [N_NET  * HD];
__device__ float g_btn [N_NODE * HD];
__device__ __align__(16) uint2 g_fh_p[NFRAG];
__device__ __align__(16) uint2 g_fh_n[NFRAG];

// ---------------------------------------------------------------------------
__global__ void k_zero() {
    int stride = gridDim.x * blockDim.x;
    int i0 = blockIdx.x * blockDim.x + threadIdx.x;
    const float4 z = make_float4(0.f, 0.f, 0.f, 0.f);
    for (int j = i0; j < N_NODE / 4; j += stride) {
        reinterpret_cast<float4*>(g_deg_out)[j] = z;
        reinterpret_cast<float4*>(g_deg_p)[j] = z;
        reinterpret_cast<float4*>(g_deg_n)[j] = z;
    }
    for (int j = i0; j < N_NET / 4; j += stride) reinterpret_cast<float4*>(g_deg_in)[j] = z;
    for (int j = i0; j < N_NET * HD / 4; j += stride) reinterpret_cast<float4*>(g_agg)[j] = z;
    for (int j = i0; j < N_NODE * HD / 4; j += stride) {
        reinterpret_cast<float4*>(g_accp)[j] = z;
        reinterpret_cast<float4*>(g_accn)[j] = z;
    }
}

// ---------------------------------------------------------------------------
__global__ void k_deg(const int* __restrict__ ps, const int* __restrict__ pd,
                      const int* __restrict__ pnd, const int* __restrict__ nrd) {
    int e = blockIdx.x * blockDim.x + threadIdx.x;
    if (e >= NEDGE) return;
    atomicAdd(&g_deg_out[ps[e]],  1.f);
    atomicAdd(&g_deg_in [pd[e]],  1.f);
    atomicAdd(&g_deg_p  [pnd[e]], 1.f);
    atomicAdd(&g_deg_n  [nrd[e]], 1.f);
}

// ---------------------------------------------------------------------------
// pins aggregation with vector reductions: one thread per (edge, quarter-row)
__global__ void k_pins(const float* __restrict__ nodef,
                       const int* __restrict__ src, const int* __restrict__ dst) {
    int t = blockIdx.x * blockDim.x + threadIdx.x;
    if (t >= NEDGE * 8) return;
    int e = t >> 3, q = t & 7;
    int s = src[e];
    float nrm = rsqrtf(fmaxf(g_deg_out[s], 1.f));
    float4 v = reinterpret_cast<const float4*>(nodef + (size_t)s * HD)[q];
    red_v4(g_agg + (size_t)dst[e] * HD + q * 4,
           v.x * nrm, v.y * nrm, v.z * nrm, v.w * nrm);
}

// ---------------------------------------------------------------------------
__global__ void k_netout(const float* __restrict__ gcw, const float* __restrict__ gcb,
                         float* __restrict__ out) {
    int t = blockIdx.x * blockDim.x + threadIdx.x;
    if (t >= N_NET * HD) return;
    int n = t >> 5, o = t & 31;
    float nrm = rsqrtf(fmaxf(g_deg_in[n], 1.f));
    float a = 0.f;
    #pragma unroll
    for (int d = 0; d < HD; d++)
        a = fmaf(g_agg[n * HD + d], gcw[d * HD + o], a);
    out[(size_t)N_NODE * HD + t] = a * nrm + gcb[o];
}

// ---------------------------------------------------------------------------
// Precompute fp16 B fragments for BOTH relations (m16n8k16 .col layout).
__global__ void k_wprep(const float* __restrict__ w0, const float* __restrict__ w1,
                        uint2* __restrict__ fh0, uint2* __restrict__ fh1) {
    int gidx = blockIdx.x * blockDim.x + threadIdx.x;
    if (gidx >= 2 * NFRAG) return;
    int rel = gidx >= NFRAG;
    int idx = gidx - rel * NFRAG;
    const float* w = rel ? w1 : w0;
    uint2* fh = rel ? fh1 : fh0;
    int lane = idx & 31, nb = (idx >> 5) & 3, i = idx >> 7;
    int o = nb * 8 + (lane >> 2);
    int k0 = (lane & 3) * 2;
    const float* row = w + ((size_t)i * HD + o) * HE;
    fh[idx] = make_uint2(f16pair(row[k0],     row[k0 + 1]),
                         f16pair(row[k0 + 8], row[k0 + 9]));
}

// ---------------------------------------------------------------------------
// Exact bias term tables for both relations in one launch.
__global__ void k_bterm(const float* __restrict__ netf, const float* __restrict__ tb,
                        const float* __restrict__ nodef, const float* __restrict__ gb) {
    int t = blockIdx.x * blockDim.x + threadIdx.x;
    if (t >= (N_NET + N_NODE) * HD) return;
    const float* feat; const float* b; float* out; int row;
    if (t < N_NET * HD) {
        feat = netf; b = tb; out = g_btp; row = t >> 5;
    } else {
        t -= N_NET * HD;
        feat = nodef; b = gb; out = g_btn; row = t >> 5;
    }
    int o = t & 31;
    float a = 0.f;
    #pragma unroll
    for (int i = 0; i < HD; i++)
        a = fmaf(feat[(size_t)row * HD + i], b[i * HD + o], a);
    out[(size_t)row * HD + o] = a;
}

// ---------------------------------------------------------------------------
// Fused NNConv, fp16 2-term scheme: D = Zh@Wh + Zl@Wh (z split to ~22 bits,
// W single fp16). blockIdx.y selects relation, TPC tiles per CTA.
__global__ void __launch_bounds__(256, 3)
k_nnconv_mma(const float* __restrict__ sf0, const float* __restrict__ ef0,
             const int* __restrict__ src0, const int* __restrict__ dst0,
             const uint2* __restrict__ gfh0, const float* __restrict__ bt0,
             float* __restrict__ acc0,
             const float* __restrict__ sf1, const float* __restrict__ ef1,
             const int* __restrict__ src1, const int* __restrict__ dst1,
             const uint2* __restrict__ gfh1, const float* __restrict__ bt1,
             float* __restrict__ acc1) {
    extern __shared__ char smem[];
    float* nf_s = (float*)smem;
    uint2* fh_s = (uint2*)(smem + FH_OFF);
    int tid = threadIdx.x;
    int rel = blockIdx.y;

    const float* srcfeat = rel ? sf1 : sf0;
    const float* efeat   = rel ? ef1 : ef0;
    const int* src       = rel ? src1 : src0;
    const int* dst       = rel ? dst1 : dst0;
    const uint2* gfh     = rel ? gfh1 : gfh0;
    const float* bterm   = rel ? bt1 : bt0;
    float* acc           = rel ? acc1 : acc0;

    // copy B fragments (32 KB) into smem once
    {
        const uint4* s1 = (const uint4*)gfh;
        uint4* d1 = (uint4*)fh_s;
        #pragma unroll
        for (int q = 0; q < (NFRAG * 8 / 16) / 256; q++)
            d1[q * 256 + tid] = s1[q * 256 + tid];
    }

    int lane = tid & 31, wid = tid >> 5;
    int r0 = lane >> 2, c0 = (lane & 3) * 2;
    int wr = wid * 16;

    #pragma unroll 1
    for (int t = 0; t < TPC; t++) {
        int tile = blockIdx.x * TPC + t;
        if (tile >= NTILES) break;
        int base = tile * TILE_M;

        __syncthreads();   // protect nf_s reuse (and fragment copy on t=0)
        for (int idx = tid; idx < TILE_M * HD; idx += 256) {
            int row = idx >> 5, col = idx & 31;
            int e = base + row;
            float v = 0.f;
            if (e < NEDGE) v = srcfeat[(size_t)src[e] * HD + col];
            nf_s[row * NF_STRIDE + col] = v;
        }
        __syncthreads();

        int e0 = base + wr + r0;
        int e1 = e0 + 8;
        bool l0 = (e0 < NEDGE), l1 = (e1 < NEDGE);

        float pf0[4] = {0.f, 0.f, 0.f, 0.f}, pf1[4] = {0.f, 0.f, 0.f, 0.f};
        if (l0) {
            float2 q = *(const float2*)(efeat + (size_t)e0 * HE + c0);
            pf0[0] = q.x; pf0[1] = q.y;
            q = *(const float2*)(efeat + (size_t)e0 * HE + c0 + 8);
            pf0[2] = q.x; pf0[3] = q.y;
        }
        if (l1) {
            float2 q = *(const float2*)(efeat + (size_t)e1 * HE + c0);
            pf1[0] = q.x; pf1[1] = q.y;
            q = *(const float2*)(efeat + (size_t)e1 * HE + c0 + 8);
            pf1[2] = q.x; pf1[3] = q.y;
        }

        float d[4][4];
        #pragma unroll
        for (int nb = 0; nb < 4; nb++)
            #pragma unroll
            for (int q = 0; q < 4; q++) d[nb][q] = 0.f;

        #pragma unroll 4
        for (int i = 0; i < HD; i++) {
            float f0 = nf_s[(wr + r0) * NF_STRIDE + i];
            float f1 = nf_s[(wr + r0 + 8) * NF_STRIDE + i];
            float z00 = f0 * pf0[0], z01 = f0 * pf0[1], z02 = f0 * pf0[2], z03 = f0 * pf0[3];
            float z10 = f1 * pf1[0], z11 = f1 * pf1[1], z12 = f1 * pf1[2], z13 = f1 * pf1[3];

            __half2 h00 = __floats2half2_rn(z00, z01);
            __half2 h10 = __floats2half2_rn(z10, z11);
            __half2 h02 = __floats2half2_rn(z02, z03);
            __half2 h12 = __floats2half2_rn(z12, z13);
            u32 ah0 = *(u32*)&h00, ah1 = *(u32*)&h10;
            u32 ah2 = *(u32*)&h02, ah3 = *(u32*)&h12;
            u32 al0 = f16pair(z00 - __low2float(h00), z01 - __high2float(h00));
            u32 al1 = f16pair(z10 - __low2float(h10), z11 - __high2float(h10));
            u32 al2 = f16pair(z02 - __low2float(h02), z03 - __high2float(h02));
            u32 al3 = f16pair(z12 - __low2float(h12), z13 - __high2float(h12));

            #pragma unroll
            for (int nb = 0; nb < 4; nb++) {
                uint2 bh = fh_s[(i * 4 + nb) * 32 + lane];
                mma_f16(d[nb], ah0, ah1, ah2, ah3, bh.x, bh.y);
                mma_f16(d[nb], al0, al1, al2, al3, bh.x, bh.y);
            }
        }

        if (l0) {
            int s0 = src[e0], dn0 = dst[e0];
            const float* bt = bterm + (size_t)s0 * HD;
            float* ap = acc + (size_t)dn0 * HD;
            #pragma unroll
            for (int nb = 0; nb < 4; nb++) {
                int o = nb * 8 + c0;
                red_v2(ap + o, d[nb][0] + bt[o], d[nb][1] + bt[o + 1]);
            }
        }
        if (l1) {
            int s1i = src[e1], dn1 = dst[e1];
            const float* bt = bterm + (size_t)s1i * HD;
            float* ap = acc + (size_t)dn1 * HD;
            #pragma unroll
            for (int nb = 0; nb < 4; nb++) {
                int o = nb * 8 + c0;
                red_v2(ap + o, d[nb][2] + bt[o], d[nb][3] + bt[o + 1]);
            }
        }
    }
}

// ---------------------------------------------------------------------------
__global__ void k_final(const float* __restrict__ pb, const float* __restrict__ nb,
                        float* __restrict__ out) {
    int t = blockIdx.x * blockDim.x + threadIdx.x;
    if (t >= N_NODE * HD) return;
    int n = t >> 5, o = t & 31;
    float p = g_accp[t] / fmaxf(g_deg_p[n], 1.f) + pb[o];
    float q = g_accn[t] / fmaxf(g_deg_n[n], 1.f) + nb[o];
    out[t] = fmaxf(p, q);
}

// ---------------------------------------------------------------------------
extern "C" void kernel_launch(void* const* d_in, const int* in_sizes, int n_in,
                              void* d_out, int out_size) {
    const float* node_feat = (const float*)d_in[0];
    const float* net_feat  = (const float*)d_in[1];
    const float* pin_feat  = (const float*)d_in[2];
    const float* edge_feat = (const float*)d_in[3];
    const float* topo_w    = (const float*)d_in[4];
    const float* topo_b    = (const float*)d_in[5];
    const float* geom_w    = (const float*)d_in[6];
    const float* geom_b    = (const float*)d_in[7];
    const float* gc_w      = (const float*)d_in[8];
    const float* gc_b      = (const float*)d_in[9];
    const float* pinned_b  = (const float*)d_in[10];
    const float* near_b    = (const float*)d_in[11];
    const int* pins_src    = (const int*)d_in[12];
    const int* pins_dst    = (const int*)d_in[13];
    const int* pinned_src  = (const int*)d_in[14];
    const int* pinned_dst  = (const int*)d_in[15];
    const int* near_src    = (const int*)d_in[16];
    const int* near_dst    = (const int*)d_in[17];
    float* out = (float*)d_out;

    cudaFuncSetAttribute(k_nnconv_mma, cudaFuncAttributeMaxDynamicSharedMemorySize, SM_TOT);

    float *accp, *accn, *btp, *btn;
    uint2 *fhp, *fhn;
    cudaGetSymbolAddress((void**)&accp, g_accp);
    cudaGetSymbolAddress((void**)&accn, g_accn);
    cudaGetSymbolAddress((void**)&btp,  g_btp);
    cudaGetSymbolAddress((void**)&btn,  g_btn);
    cudaGetSymbolAddress((void**)&fhp,  g_fh_p);
    cudaGetSymbolAddress((void**)&fhn,  g_fh_n);

    // Fork-join concurrency: side stream runs the pins-relation chain while the
    // origin stream runs the NNConv chain.
    cudaStream_t s2;
    cudaStreamCreateWithFlags(&s2, cudaStreamNonBlocking);
    cudaEvent_t evFork, evZero, evDeg, evJoin;
    cudaEventCreateWithFlags(&evFork, cudaEventDisableTiming);
    cudaEventCreateWithFlags(&evZero, cudaEventDisableTiming);
    cudaEventCreateWithFlags(&evDeg,  cudaEventDisableTiming);
    cudaEventCreateWithFlags(&evJoin, cudaEventDisableTiming);

    cudaEventRecord(evFork, 0);
    cudaStreamWaitEvent(s2, evFork, 0);

    // --- side stream: zero + degrees + pins relation ---
    k_zero<<<512, 256, 0, s2>>>();
    cudaEventRecord(evZero, s2);
    k_deg<<<(NEDGE + 255) / 256, 256, 0, s2>>>(pins_src, pins_dst, pinned_dst, near_dst);
    cudaEventRecord(evDeg, s2);
    k_pins<<<(NEDGE * 8 + 255) / 256, 256, 0, s2>>>(node_feat, pins_src, pins_dst);
    k_netout<<<(N_NET * HD + 255) / 256, 256, 0, s2>>>(gc_w, gc_b, out);
    cudaEventRecord(evJoin, s2);

    // --- origin stream: fragment/bias prep + NNConv + final ---
    k_wprep<<<(2 * NFRAG + 255) / 256, 256>>>(topo_w, geom_w, fhp, fhn);
    k_bterm<<<((N_NET + N_NODE) * HD + 255) / 256, 256>>>(net_feat, topo_b,
                                                          node_feat, geom_b);
    cudaStreamWaitEvent(0, evZero, 0);   // acc buffers zeroed
    dim3 grid(GRIDX, 2);
    k_nnconv_mma<<<grid, 256, SM_TOT>>>(net_feat,  pin_feat,  pinned_src, pinned_dst,
                                        fhp, btp, accp,
                                        node_feat, edge_feat, near_src,  near_dst,
                                        fhn, btn, accn);
    cudaStreamWaitEvent(0, evDeg, 0);    // g_deg_p / g_deg_n ready
    k_final<<<(N_NODE * HD + 255) / 256, 256>>>(pinned_b, near_b, out);
    cudaStreamWaitEvent(0, evJoin, 0);   // join side stream (net_out part of out)
}

// round 10
// speedup vs baseline: 4.4437x; 1.1947x over previous
#include <cuda_runtime.h>
#include <cuda_fp16.h>
#include <math.h>
#include <stdint.h>

#define N_NODE 80000
#define N_NET  20000
#define NEDGE  150000
#define HD     32
#define HE     16

#define TILE_M 128
#define NTILES ((NEDGE + TILE_M - 1) / TILE_M)   // 1172
#define GRIDX  222                                // x2 relations = 444 CTAs = 148 SMs * 3
#define NFRAG  (HD * 4 * 32)                      // 4096 fragment slots (i, nb, lane)

// smem layout (bytes)
#define NF_STRIDE 33
#define NF_BYTES  (TILE_M * NF_STRIDE * 4)        // 16896 (16-aligned)
#define FH_OFF    NF_BYTES
#define SM_TOT    (NF_BYTES + NFRAG * 8)          // 49664

typedef unsigned int u32;

// ---------------- helpers ----------------
__device__ __forceinline__ u32 f16pair(float lo, float hi) {
    __half2 h = __floats2half2_rn(lo, hi);        // x=lo, y=hi
    return *reinterpret_cast<u32*>(&h);
}
__device__ __forceinline__ void mma_f16(float* d, u32 a0, u32 a1, u32 a2, u32 a3,
                                        u32 b0, u32 b1) {
    asm volatile(
        "mma.sync.aligned.m16n8k16.row.col.f32.f16.f16.f32 "
        "{%0,%1,%2,%3}, {%4,%5,%6,%7}, {%8,%9}, {%0,%1,%2,%3};"
        : "+f"(d[0]), "+f"(d[1]), "+f"(d[2]), "+f"(d[3])
        : "r"(a0), "r"(a1), "r"(a2), "r"(a3), "r"(b0), "r"(b1));
}
__device__ __forceinline__ void red_v2(float* p, float a, float b) {
    asm volatile("red.global.add.v2.f32 [%0], {%1, %2};"
                 :: "l"(p), "f"(a), "f"(b) : "memory");
}
__device__ __forceinline__ void red_v4(float* p, float a, float b, float c, float d) {
    asm volatile("red.global.add.v4.f32 [%0], {%1, %2, %3, %4};"
                 :: "l"(p), "f"(a), "f"(b), "f"(c), "f"(d) : "memory");
}

// ---- scratch (device globals; no allocation allowed) ----
__device__ float g_deg_out[N_NODE];
__device__ float g_deg_in [N_NET];
__device__ float g_deg_p  [N_NODE];
__device__ float g_deg_n  [N_NODE];
__device__ __align__(16) float g_agg [N_NET * HD];
__device__ __align__(16) float g_accp[N_NODE * HD];
__device__ __align__(16) float g_accn[N_NODE * HD];
__device__ float g_btp [N_NET  * HD];
__device__ float g_btn [N_NODE * HD];
__device__ __align__(16) uint2 g_fh_p[NFRAG];
__device__ __align__(16) uint2 g_fh_n[NFRAG];

// ---------------------------------------------------------------------------
__global__ void k_zero() {
    int stride = gridDim.x * blockDim.x;
    int i0 = blockIdx.x * blockDim.x + threadIdx.x;
    const float4 z = make_float4(0.f, 0.f, 0.f, 0.f);
    for (int j = i0; j < N_NODE / 4; j += stride) {
        reinterpret_cast<float4*>(g_deg_out)[j] = z;
        reinterpret_cast<float4*>(g_deg_p)[j] = z;
        reinterpret_cast<float4*>(g_deg_n)[j] = z;
    }
    for (int j = i0; j < N_NET / 4; j += stride) reinterpret_cast<float4*>(g_deg_in)[j] = z;
    for (int j = i0; j < N_NET * HD / 4; j += stride) reinterpret_cast<float4*>(g_agg)[j] = z;
    for (int j = i0; j < N_NODE * HD / 4; j += stride) {
        reinterpret_cast<float4*>(g_accp)[j] = z;
        reinterpret_cast<float4*>(g_accn)[j] = z;
    }
}

// ---------------------------------------------------------------------------
__global__ void k_deg(const int* __restrict__ ps, const int* __restrict__ pd,
                      const int* __restrict__ pnd, const int* __restrict__ nrd) {
    int e = blockIdx.x * blockDim.x + threadIdx.x;
    if (e >= NEDGE) return;
    atomicAdd(&g_deg_out[ps[e]],  1.f);
    atomicAdd(&g_deg_in [pd[e]],  1.f);
    atomicAdd(&g_deg_p  [pnd[e]], 1.f);
    atomicAdd(&g_deg_n  [nrd[e]], 1.f);
}

// ---------------------------------------------------------------------------
// pins aggregation with vector reductions: one thread per (edge, quarter-row)
__global__ void k_pins(const float* __restrict__ nodef,
                       const int* __restrict__ src, const int* __restrict__ dst) {
    int t = blockIdx.x * blockDim.x + threadIdx.x;
    if (t >= NEDGE * 8) return;
    int e = t >> 3, q = t & 7;
    int s = src[e];
    float nrm = rsqrtf(fmaxf(g_deg_out[s], 1.f));
    float4 v = reinterpret_cast<const float4*>(nodef + (size_t)s * HD)[q];
    red_v4(g_agg + (size_t)dst[e] * HD + q * 4,
           v.x * nrm, v.y * nrm, v.z * nrm, v.w * nrm);
}

// ---------------------------------------------------------------------------
__global__ void k_netout(const float* __restrict__ gcw, const float* __restrict__ gcb,
                         float* __restrict__ out) {
    int t = blockIdx.x * blockDim.x + threadIdx.x;
    if (t >= N_NET * HD) return;
    int n = t >> 5, o = t & 31;
    float nrm = rsqrtf(fmaxf(g_deg_in[n], 1.f));
    float a = 0.f;
    #pragma unroll
    for (int d = 0; d < HD; d++)
        a = fmaf(g_agg[n * HD + d], gcw[d * HD + o], a);
    out[(size_t)N_NODE * HD + t] = a * nrm + gcb[o];
}

// ---------------------------------------------------------------------------
// Precompute fp16 B fragments for BOTH relations (m16n8k16 .col layout).
__global__ void k_wprep(const float* __restrict__ w0, const float* __restrict__ w1,
                        uint2* __restrict__ fh0, uint2* __restrict__ fh1) {
    int gidx = blockIdx.x * blockDim.x + threadIdx.x;
    if (gidx >= 2 * NFRAG) return;
    int rel = gidx >= NFRAG;
    int idx = gidx - rel * NFRAG;
    const float* w = rel ? w1 : w0;
    uint2* fh = rel ? fh1 : fh0;
    int lane = idx & 31, nb = (idx >> 5) & 3, i = idx >> 7;
    int o = nb * 8 + (lane >> 2);
    int k0 = (lane & 3) * 2;
    const float* row = w + ((size_t)i * HD + o) * HE;
    fh[idx] = make_uint2(f16pair(row[k0],     row[k0 + 1]),
                         f16pair(row[k0 + 8], row[k0 + 9]));
}

// ---------------------------------------------------------------------------
// Exact bias term tables for both relations in one launch.
__global__ void k_bterm(const float* __restrict__ netf, const float* __restrict__ tb,
                        const float* __restrict__ nodef, const float* __restrict__ gb) {
    int t = blockIdx.x * blockDim.x + threadIdx.x;
    if (t >= (N_NET + N_NODE) * HD) return;
    const float* feat; const float* b; float* out; int row;
    if (t < N_NET * HD) {
        feat = netf; b = tb; out = g_btp; row = t >> 5;
    } else {
        t -= N_NET * HD;
        feat = nodef; b = gb; out = g_btn; row = t >> 5;
    }
    int o = t & 31;
    float a = 0.f;
    #pragma unroll
    for (int i = 0; i < HD; i++)
        a = fmaf(feat[(size_t)row * HD + i], b[i * HD + o], a);
    out[(size_t)row * HD + o] = a;
}

// ---------------------------------------------------------------------------
// Fused NNConv, single-pass fp16: D = Zh@Wh (z computed fp32, one rounding).
// Persistent grid-stride over tiles; blockIdx.y selects relation.
__global__ void __launch_bounds__(256, 3)
k_nnconv_mma(const float* __restrict__ sf0, const float* __restrict__ ef0,
             const int* __restrict__ src0, const int* __restrict__ dst0,
             const uint2* __restrict__ gfh0, const float* __restrict__ bt0,
             float* __restrict__ acc0,
             const float* __restrict__ sf1, const float* __restrict__ ef1,
             const int* __restrict__ src1, const int* __restrict__ dst1,
             const uint2* __restrict__ gfh1, const float* __restrict__ bt1,
             float* __restrict__ acc1) {
    extern __shared__ char smem[];
    float* nf_s = (float*)smem;
    uint2* fh_s = (uint2*)(smem + FH_OFF);
    int tid = threadIdx.x;
    int rel = blockIdx.y;

    const float* srcfeat = rel ? sf1 : sf0;
    const float* efeat   = rel ? ef1 : ef0;
    const int* src       = rel ? src1 : src0;
    const int* dst       = rel ? dst1 : dst0;
    const uint2* gfh     = rel ? gfh1 : gfh0;
    const float* bterm   = rel ? bt1 : bt0;
    float* acc           = rel ? acc1 : acc0;

    // copy B fragments (32 KB) into smem once
    {
        const uint4* s1 = (const uint4*)gfh;
        uint4* d1 = (uint4*)fh_s;
        #pragma unroll
        for (int q = 0; q < (NFRAG * 8 / 16) / 256; q++)
            d1[q * 256 + tid] = s1[q * 256 + tid];
    }

    int lane = tid & 31, wid = tid >> 5;
    int r0 = lane >> 2, c0 = (lane & 3) * 2;
    int wr = wid * 16;

    #pragma unroll 1
    for (int tile = blockIdx.x; tile < NTILES; tile += GRIDX) {
        int base = tile * TILE_M;

        __syncthreads();   // protect nf_s reuse (and fragment copy on first iter)
        for (int idx = tid; idx < TILE_M * HD; idx += 256) {
            int row = idx >> 5, col = idx & 31;
            int e = base + row;
            float v = 0.f;
            if (e < NEDGE) v = srcfeat[(size_t)src[e] * HD + col];
            nf_s[row * NF_STRIDE + col] = v;
        }
        __syncthreads();

        int e0 = base + wr + r0;
        int e1 = e0 + 8;
        bool l0 = (e0 < NEDGE), l1 = (e1 < NEDGE);

        float pf0[4] = {0.f, 0.f, 0.f, 0.f}, pf1[4] = {0.f, 0.f, 0.f, 0.f};
        if (l0) {
            float2 q = *(const float2*)(efeat + (size_t)e0 * HE + c0);
            pf0[0] = q.x; pf0[1] = q.y;
            q = *(const float2*)(efeat + (size_t)e0 * HE + c0 + 8);
            pf0[2] = q.x; pf0[3] = q.y;
        }
        if (l1) {
            float2 q = *(const float2*)(efeat + (size_t)e1 * HE + c0);
            pf1[0] = q.x; pf1[1] = q.y;
            q = *(const float2*)(efeat + (size_t)e1 * HE + c0 + 8);
            pf1[2] = q.x; pf1[3] = q.y;
        }

        float d[4][4];
        #pragma unroll
        for (int nb = 0; nb < 4; nb++)
            #pragma unroll
            for (int q = 0; q < 4; q++) d[nb][q] = 0.f;

        #pragma unroll 4
        for (int i = 0; i < HD; i++) {
            float f0 = nf_s[(wr + r0) * NF_STRIDE + i];
            float f1 = nf_s[(wr + r0 + 8) * NF_STRIDE + i];
            u32 ah0 = f16pair(f0 * pf0[0], f0 * pf0[1]);
            u32 ah1 = f16pair(f1 * pf1[0], f1 * pf1[1]);
            u32 ah2 = f16pair(f0 * pf0[2], f0 * pf0[3]);
            u32 ah3 = f16pair(f1 * pf1[2], f1 * pf1[3]);
            #pragma unroll
            for (int nb = 0; nb < 4; nb++) {
                uint2 bh = fh_s[(i * 4 + nb) * 32 + lane];
                mma_f16(d[nb], ah0, ah1, ah2, ah3, bh.x, bh.y);
            }
        }

        if (l0) {
            int s0 = src[e0], dn0 = dst[e0];
            const float* bt = bterm + (size_t)s0 * HD;
            float* ap = acc + (size_t)dn0 * HD;
            #pragma unroll
            for (int nb = 0; nb < 4; nb++) {
                int o = nb * 8 + c0;
                red_v2(ap + o, d[nb][0] + bt[o], d[nb][1] + bt[o + 1]);
            }
        }
        if (l1) {
            int s1i = src[e1], dn1 = dst[e1];
            const float* bt = bterm + (size_t)s1i * HD;
            float* ap = acc + (size_t)dn1 * HD;
            #pragma unroll
            for (int nb = 0; nb < 4; nb++) {
                int o = nb * 8 + c0;
                red_v2(ap + o, d[nb][2] + bt[o], d[nb][3] + bt[o + 1]);
            }
        }
    }
}

// ---------------------------------------------------------------------------
__global__ void k_final(const float* __restrict__ pb, const float* __restrict__ nb,
                        float* __restrict__ out) {
    int t = blockIdx.x * blockDim.x + threadIdx.x;
    if (t >= N_NODE * HD) return;
    int n = t >> 5, o = t & 31;
    float p = g_accp[t] / fmaxf(g_deg_p[n], 1.f) + pb[o];
    float q = g_accn[t] / fmaxf(g_deg_n[n], 1.f) + nb[o];
    out[t] = fmaxf(p, q);
}

// ---------------------------------------------------------------------------
extern "C" void kernel_launch(void* const* d_in, const int* in_sizes, int n_in,
                              void* d_out, int out_size) {
    const float* node_feat = (const float*)d_in[0];
    const float* net_feat  = (const float*)d_in[1];
    const float* pin_feat  = (const float*)d_in[2];
    const float* edge_feat = (const float*)d_in[3];
    const float* topo_w    = (const float*)d_in[4];
    const float* topo_b    = (const float*)d_in[5];
    const float* geom_w    = (const float*)d_in[6];
    const float* geom_b    = (const float*)d_in[7];
    const float* gc_w      = (const float*)d_in[8];
    const float* gc_b      = (const float*)d_in[9];
    const float* pinned_b  = (const float*)d_in[10];
    const float* near_b    = (const float*)d_in[11];
    const int* pins_src    = (const int*)d_in[12];
    const int* pins_dst    = (const int*)d_in[13];
    const int* pinned_src  = (const int*)d_in[14];
    const int* pinned_dst  = (const int*)d_in[15];
    const int* near_src    = (const int*)d_in[16];
    const int* near_dst    = (const int*)d_in[17];
    float* out = (float*)d_out;

    cudaFuncSetAttribute(k_nnconv_mma, cudaFuncAttributeMaxDynamicSharedMemorySize, SM_TOT);

    float *accp, *accn, *btp, *btn;
    uint2 *fhp, *fhn;
    cudaGetSymbolAddress((void**)&accp, g_accp);
    cudaGetSymbolAddress((void**)&accn, g_accn);
    cudaGetSymbolAddress((void**)&btp,  g_btp);
    cudaGetSymbolAddress((void**)&btn,  g_btn);
    cudaGetSymbolAddress((void**)&fhp,  g_fh_p);
    cudaGetSymbolAddress((void**)&fhn,  g_fh_n);

    // Fork-join concurrency: side stream runs the pins-relation chain while the
    // origin stream runs the NNConv chain.
    cudaStream_t s2;
    cudaStreamCreateWithFlags(&s2, cudaStreamNonBlocking);
    cudaEvent_t evFork, evZero, evDeg, evJoin;
    cudaEventCreateWithFlags(&evFork, cudaEventDisableTiming);
    cudaEventCreateWithFlags(&evZero, cudaEventDisableTiming);
    cudaEventCreateWithFlags(&evDeg,  cudaEventDisableTiming);
    cudaEventCreateWithFlags(&evJoin, cudaEventDisableTiming);

    cudaEventRecord(evFork, 0);
    cudaStreamWaitEvent(s2, evFork, 0);

    // --- side stream: zero + degrees + pins relation ---
    k_zero<<<512, 256, 0, s2>>>();
    cudaEventRecord(evZero, s2);
    k_deg<<<(NEDGE + 255) / 256, 256, 0, s2>>>(pins_src, pins_dst, pinned_dst, near_dst);
    cudaEventRecord(evDeg, s2);
    k_pins<<<(NEDGE * 8 + 255) / 256, 256, 0, s2>>>(node_feat, pins_src, pins_dst);
    k_netout<<<(N_NET * HD + 255) / 256, 256, 0, s2>>>(gc_w, gc_b, out);
    cudaEventRecord(evJoin, s2);

    // --- origin stream: fragment/bias prep + NNConv + final ---
    k_wprep<<<(2 * NFRAG + 255) / 256, 256>>>(topo_w, geom_w, fhp, fhn);
    k_bterm<<<((N_NET + N_NODE) * HD + 255) / 256, 256>>>(net_feat, topo_b,
                                                          node_feat, geom_b);
    cudaStreamWaitEvent(0, evZero, 0);   // acc buffers zeroed
    dim3 grid(GRIDX, 2);
    k_nnconv_mma<<<grid, 256, SM_TOT>>>(net_feat,  pin_feat,  pinned_src, pinned_dst,
                                        fhp, btp, accp,
                                        node_feat, edge_feat, near_src,  near_dst,
                                        fhn, btn, accn);
    cudaStreamWaitEvent(0, evDeg, 0);    // g_deg_p / g_deg_n ready
    k_final<<<(N_NODE * HD + 255) / 256, 256>>>(pinned_b, near_b, out);
    cudaStreamWaitEvent(0, evJoin, 0);   // join side stream (net_out part of out)
}